// round 10
// baseline (speedup 1.0000x reference)
#include <cuda_runtime.h>
#include <math.h>
#include <cstdint>

// ---------------- problem constants ----------------
#define BATCH 512
#define NH 4
#define KD 16
#define DD 64
#define DIM 256
#define QO 96
#define RESX 14
#define NPIX 196

typedef unsigned long long ull;

// global scratch
__device__ __align__(128) float g_cat_t[(size_t)BATCH * NPIX * DIM];
__device__ __align__(128) float g_wt[DIM * DIM];
__device__ __align__(128) float g_abmat[NH * NPIX * NPIX + 16];
__device__ __align__(128) float g_abrmax[NH * NPIX];

__device__ __forceinline__ float to_tf32(float x) {
    float r; asm("cvt.rna.satfinite.tf32.f32 %0, %1;" : "=f"(r) : "f"(x)); return r;
}
__device__ __forceinline__ uint32_t smem_u32(const void* p) {
    uint32_t a;
    asm("{ .reg .u64 t; cvta.to.shared.u64 t, %1; cvt.u32.u64 %0, t; }" : "=r"(a) : "l"(p));
    return a;
}
// fragment-pack permutation: block of 8 cols -> pairs (j, j+4) adjacent
__device__ __forceinline__ int pidx(int m) {
    return (m & ~7) + ((m & 3) * 2) + ((m >> 2) & 1);
}

// ---------------- cp.async helpers ----------------
#define CP_ASYNC16(dst_u32, src_ptr) \
    asm volatile("cp.async.cg.shared.global [%0], [%1], 16;" :: "r"(dst_u32), "l"(src_ptr))
#define CP_COMMIT() asm volatile("cp.async.commit_group;" ::: "memory")
#define CP_WAIT0()  asm volatile("cp.async.wait_group 0;" ::: "memory")

// ---------------- mma.sync tf32 m16n8k8 ----------------
__device__ __forceinline__ void mma_tf32(float* d, const uint32_t* a, const uint32_t* b) {
    asm volatile(
        "mma.sync.aligned.m16n8k8.row.col.f32.tf32.tf32.f32 "
        "{%0,%1,%2,%3}, {%4,%5,%6,%7}, {%8,%9}, {%0,%1,%2,%3};"
        : "+f"(d[0]), "+f"(d[1]), "+f"(d[2]), "+f"(d[3])
        : "r"(a[0]), "r"(a[1]), "r"(a[2]), "r"(a[3]), "r"(b[0]), "r"(b[1]));
}
__device__ __forceinline__ void mma8(float* d, float a0, float a1, float a2, float a3,
                                     float b0, float b1) {
    uint32_t A[4] = {__float_as_uint(a0), __float_as_uint(a1),
                     __float_as_uint(a2), __float_as_uint(a3)};
    uint32_t B[2] = {__float_as_uint(b0), __float_as_uint(b1)};
    mma_tf32(d, A, B);
}

// ---------------- cascade smem layout (float offsets) ----------------
#define CF_FEAT 0            // 200 x 68
#define CF_QT   13600        // 224 x 18
#define CF_KT   17632        // 224 x 18
#define CF_QG   21664        // 224 x 18
#define CF_V    25696        // 64 x 200 packed
#define CF_WQ   38496        // 96 x 68
#define CF_QSC  45024
#define CF_QBI  45120
#define CF_DSC  45216
#define CF_DBI  45232
#define CF_DWW  45248
#define CF_KMX  45648        // 1 int: max ||k_m||^2 bits
#define CF_END  45652
#define SMEM1_BYTES (CF_END * 4)

__global__ void __launch_bounds__(512, 1)
cascade_kernel(const float* __restrict__ x,
               const float* __restrict__ qkv_w,
               const float* __restrict__ qkv_scale,
               const float* __restrict__ qkv_bias,
               const float* __restrict__ dw_w,
               const float* __restrict__ dw_scale,
               const float* __restrict__ dw_bias)
{
    extern __shared__ float sm[];
    float* featT = sm + CF_FEAT;
    float* qT    = sm + CF_QT;
    float* kT    = sm + CF_KT;
    float* qgT   = sm + CF_QG;
    float* vv    = sm + CF_V;
    float* wq    = sm + CF_WQ;
    float* qsc   = sm + CF_QSC;
    float* qbi   = sm + CF_QBI;
    float* dsc   = sm + CF_DSC;
    float* dbi   = sm + CF_DBI;
    float* dww   = sm + CF_DWW;
    int*   kmx   = (int*)(sm + CF_KMX);

    const int b    = blockIdx.x;
    const int tid  = threadIdx.x;
    const int warp = tid >> 5;    // 0..15
    const int lane = tid & 31;
    const int g    = lane >> 2;   // 0..7
    const int tig  = lane & 3;    // 0..3

    // one-time zero padding (qgT + kT pad rows; featT pad rows; vv pad slots)
    for (int idx = tid; idx < 28 * 18; idx += 512) {
        qgT[196 * 18 + idx] = 0.f;
        kT[196 * 18 + idx] = 0.f;
    }
    if (tid < 4 * 68) featT[196 * 68 + tid] = 0.f;
    if (tid < 256) {
        int d = tid >> 2, s = tid & 3;
        vv[d * 200 + 193 + 2 * s] = 0.f;
    }
    __syncthreads();

    for (int i = 0; i < NH; i++) {
        // ---------- Phase A: feat accumulate + staging ----------
        {
            const float* xb = x + ((size_t)b * DIM + i * DD) * NPIX;
            if (i == 0) {
                for (int idx = tid; idx < DD * NPIX; idx += 512) {
                    int c = idx / NPIX, n = idx - c * NPIX;
                    featT[n * 68 + c] = to_tf32(xb[idx]);
                }
            } else {
                for (int idx = tid; idx < DD * NPIX; idx += 512) {
                    int c = idx / NPIX, n = idx - c * NPIX;
                    featT[n * 68 + c] = to_tf32(featT[n * 68 + c] + xb[idx]);
                }
            }
            for (int idx = tid; idx < QO * 64; idx += 512)
                wq[(idx >> 6) * 68 + (idx & 63)] = to_tf32(qkv_w[i * QO * 64 + idx]);
            if (tid < 400) dww[tid] = dw_w[i * 400 + tid];
            if (tid >= 400 && tid < 416) {
                int c = tid - 400;
                dsc[c] = dw_scale[i * KD + c]; dbi[c] = dw_bias[i * KD + c];
            }
            if (tid >= 416) {
                int o = tid - 416;
                qsc[o] = qkv_scale[i * QO + o]; qbi[o] = qkv_bias[i * QO + o];
            }
            if (tid == 0) *kmx = 0;   // positive-float bits compare as int
        }
        __syncthreads();

        // ---------- Phase B: QKV via mma, 75 (nt,mp) tasks over 16 warps ----------
        for (int t = warp; t < 75; t += 16) {
            const int nt = t / 3, mp = t - nt * 3;
            const int nb0 = nt * 8;
            float B0[8], B1[8];
            #pragma unroll
            for (int ks = 0; ks < 8; ks++) {
                B0[ks] = featT[(nb0 + g) * 68 + ks * 8 + tig];
                B1[ks] = featT[(nb0 + g) * 68 + ks * 8 + tig + 4];
            }
            const int oX = (2 * mp) * 16, oY = (2 * mp + 1) * 16;
            float dd0[4] = {0.f, 0.f, 0.f, 0.f};
            float dd1[4] = {0.f, 0.f, 0.f, 0.f};
            #pragma unroll
            for (int ks = 0; ks < 8; ks++) {
                mma8(dd0, wq[(oX + g) * 68 + ks * 8 + tig],
                          wq[(oX + g + 8) * 68 + ks * 8 + tig],
                          wq[(oX + g) * 68 + ks * 8 + tig + 4],
                          wq[(oX + g + 8) * 68 + ks * 8 + tig + 4],
                          B0[ks], B1[ks]);
                mma8(dd1, wq[(oY + g) * 68 + ks * 8 + tig],
                          wq[(oY + g + 8) * 68 + ks * 8 + tig],
                          wq[(oY + g) * 68 + ks * 8 + tig + 4],
                          wq[(oY + g + 8) * 68 + ks * 8 + tig + 4],
                          B0[ks], B1[ks]);
            }
            #pragma unroll
            for (int h = 0; h < 2; h++) {
                const int mt = 2 * mp + h;
                float* dd = h ? dd1 : dd0;
                const int oA = mt * 16 + g, oB = oA + 8;
                const float sA = qsc[oA], bA = qbi[oA];
                const float sB = qsc[oB], bB = qbi[oB];
                float y0 = dd[0] * sA + bA, y1 = dd[1] * sA + bA;
                float y2 = dd[2] * sB + bB, y3 = dd[3] * sB + bB;
                const int nc = nb0 + 2 * tig;
                if (mt == 0) {
                    qT[nc * 18 + oA] = y0; qT[(nc + 1) * 18 + oA] = y1;
                    qT[nc * 18 + oB] = y2; qT[(nc + 1) * 18 + oB] = y3;
                } else if (mt == 1) {
                    int c0 = oA - 16, c1 = oB - 16;
                    kT[nc * 18 + c0] = to_tf32(y0); kT[(nc + 1) * 18 + c0] = to_tf32(y1);
                    kT[nc * 18 + c1] = to_tf32(y2); kT[(nc + 1) * 18 + c1] = to_tf32(y3);
                } else {
                    int dA = oA - 32, dB = oB - 32;
                    if (nc < 196) {
                        vv[dA * 200 + pidx(nc)] = to_tf32(y0);
                        vv[dB * 200 + pidx(nc)] = to_tf32(y2);
                    }
                    if (nc + 1 < 196) {
                        vv[dA * 200 + pidx(nc + 1)] = to_tf32(y1);
                        vv[dB * 200 + pidx(nc + 1)] = to_tf32(y3);
                    }
                }
            }
        }
        __syncthreads();

        // ---------- Phase C: depthwise conv + GELU + residual, and max||k||^2 ----------
        if (tid < 196) {
            float s2 = 0.f;
            #pragma unroll
            for (int c = 0; c < KD; c++) {
                float kv = kT[tid * 18 + c];
                s2 += kv * kv;
            }
            atomicMax(kmx, __float_as_int(s2));
        }
        for (int t = tid; t < KD * NPIX; t += 512) {
            int n = t >> 4, c = t & 15;
            int py = n / RESX, px = n - py * RESX;
            float s = 0.f;
            #pragma unroll
            for (int dy = 0; dy < 5; dy++) {
                int yy = py + dy - 2;
                if (yy < 0 || yy >= RESX) continue;
                #pragma unroll
                for (int dx = 0; dx < 5; dx++) {
                    int xx = px + dx - 2;
                    if (xx < 0 || xx >= RESX) continue;
                    s += dww[c * 25 + dy * 5 + dx] * qT[(yy * RESX + xx) * 18 + c];
                }
            }
            float dq = s * dsc[c] + dbi[c];
            float gl = 0.5f * dq * (1.0f + erff(dq * 0.70710678118654752440f));
            qgT[n * 18 + c] = to_tf32(gl + qT[n * 18 + c]);
        }
        __syncthreads();

        // ---------- Phase D: warp-owned 16-row stripes, single-pass softmax ----------
        const float* abm = g_abmat + (size_t)i * (NPIX * NPIX);
        const float* abrm = g_abrmax + i * NPIX;
        float* gcb = g_cat_t + ((size_t)b * NPIX) * DIM + i * DD;

        if (warp < 13) {
            const int r0 = warp * 16;
            // qg A-frags
            float aq0 = qgT[(r0 + g) * 18 + tig],      aq1 = qgT[(r0 + g + 8) * 18 + tig];
            float aq2 = qgT[(r0 + g) * 18 + tig + 4],  aq3 = qgT[(r0 + g + 8) * 18 + tig + 4];
            float aq4 = qgT[(r0 + g) * 18 + tig + 8],  aq5 = qgT[(r0 + g + 8) * 18 + tig + 8];
            float aq6 = qgT[(r0 + g) * 18 + tig + 12], aq7 = qgT[(r0 + g + 8) * 18 + tig + 12];
            const int ngA = min(r0 + g, 195), ngB = min(r0 + g + 8, 195);
            const float* abrA = abm + (size_t)ngA * NPIX;
            const float* abrB = abm + (size_t)ngB * NPIX;
            const int m0l = 2 * tig;

            // exponent shift: B_row = 0.25*||qg_row||*maxK + rowmax(bias)
            const float kmaxn = sqrtf(__int_as_float(*kmx));
            float qnA = aq0 * aq0 + aq2 * aq2 + aq4 * aq4 + aq6 * aq6;
            float qnB = aq1 * aq1 + aq3 * aq3 + aq5 * aq5 + aq7 * aq7;
            qnA += __shfl_xor_sync(0xffffffffu, qnA, 1);
            qnA += __shfl_xor_sync(0xffffffffu, qnA, 2);
            qnB += __shfl_xor_sync(0xffffffffu, qnB, 1);
            qnB += __shfl_xor_sync(0xffffffffu, qnB, 2);
            const float Mg  = 0.25f * sqrtf(qnA) * kmaxn + abrm[ngA];
            const float Mg8 = 0.25f * sqrtf(qnB) * kmaxn + abrm[ngB];

            // single pass: QK + exp + AV (P stays in registers)
            float o[8][4];
            #pragma unroll
            for (int j = 0; j < 8; j++) { o[j][0] = o[j][1] = o[j][2] = o[j][3] = 0.f; }
            float lg = 0.f, lg8 = 0.f;
            const int srcA = (g << 2) | (tig >> 1);
            const int srcB = srcA + 2;
            const bool odd = (tig & 1);

            #pragma unroll 5
            for (int nt = 0; nt < 25; nt++) {
                const int mm0 = nt * 8;
                float b00 = kT[(mm0 + g) * 18 + tig],     b01 = kT[(mm0 + g) * 18 + tig + 4];
                float b10 = kT[(mm0 + g) * 18 + tig + 8], b11 = kT[(mm0 + g) * 18 + tig + 12];
                float dd[4] = {0.f, 0.f, 0.f, 0.f};
                mma8(dd, aq0, aq1, aq2, aq3, b00, b01);
                mma8(dd, aq4, aq5, aq6, aq7, b10, b11);
                const int m0 = mm0 + m0l;
                float2 abA = *(const float2*)&abrA[m0];
                float2 abB = *(const float2*)&abrB[m0];
                float s00 = dd[0] * 0.25f + abA.x;
                float s01 = dd[1] * 0.25f + abA.y;
                float s10 = dd[2] * 0.25f + abB.x;
                float s11 = dd[3] * 0.25f + abB.y;
                if (m0 >= NPIX)     { s00 = -1e30f; s10 = -1e30f; }
                if (m0 + 1 >= NPIX) { s01 = -1e30f; s11 = -1e30f; }
                float p00 = to_tf32(__expf(s00 - Mg));
                float p01 = to_tf32(__expf(s01 - Mg));
                float p10 = to_tf32(__expf(s10 - Mg8));
                float p11 = to_tf32(__expf(s11 - Mg8));
                lg  += p00 + p01;
                lg8 += p10 + p11;
                // re-lay D-frag cols (2tig,2tig+1) -> A-frag cols (tig, tig+4)
                float t0 = __shfl_sync(0xffffffffu, p00, srcA);
                float t1 = __shfl_sync(0xffffffffu, p01, srcA);
                float a0 = odd ? t1 : t0;
                float u0 = __shfl_sync(0xffffffffu, p10, srcA);
                float u1 = __shfl_sync(0xffffffffu, p11, srcA);
                float a1 = odd ? u1 : u0;
                float t2 = __shfl_sync(0xffffffffu, p00, srcB);
                float t3 = __shfl_sync(0xffffffffu, p01, srcB);
                float a2 = odd ? t3 : t2;
                float u2 = __shfl_sync(0xffffffffu, p10, srcB);
                float u3 = __shfl_sync(0xffffffffu, p11, srcB);
                float a3 = odd ? u3 : u2;
                #pragma unroll
                for (int j = 0; j < 8; j++) {
                    float2 bv = *(const float2*)&vv[(j * 8 + g) * 200 + mm0 + m0l];
                    mma8(o[j], a0, a1, a2, a3, bv.x, bv.y);
                }
            }
            lg  += __shfl_xor_sync(0xffffffffu, lg, 1);
            lg  += __shfl_xor_sync(0xffffffffu, lg, 2);
            lg8 += __shfl_xor_sync(0xffffffffu, lg8, 1);
            lg8 += __shfl_xor_sync(0xffffffffu, lg8, 2);
            float ivg = 1.0f / lg, ivg8 = 1.0f / lg8;

            const int nA = r0 + g, nB = r0 + g + 8;
            #pragma unroll
            for (int j = 0; j < 8; j++) {
                const int dc = j * 8 + 2 * tig;
                if (nA < NPIX) {
                    float v0 = o[j][0] * ivg, v1 = o[j][1] * ivg;
                    *(float2*)&featT[nA * 68 + dc] = make_float2(v0, v1);
                    *(float2*)&gcb[(size_t)nA * DIM + dc] =
                        make_float2(to_tf32(fmaxf(v0, 0.f)), to_tf32(fmaxf(v1, 0.f)));
                }
                if (nB < NPIX) {
                    float v2 = o[j][2] * ivg8, v3 = o[j][3] * ivg8;
                    *(float2*)&featT[nB * 68 + dc] = make_float2(v2, v3);
                    *(float2*)&gcb[(size_t)nB * DIM + dc] =
                        make_float2(to_tf32(fmaxf(v2, 0.f)), to_tf32(fmaxf(v3, 0.f)));
                }
            }
        }
        __syncthreads();
    }
}

// ---------------- prep kernels ----------------
__global__ void wprep_kernel(const float* __restrict__ proj_w) {
    int idx = blockIdx.x * 256 + threadIdx.x;
    g_wt[idx] = to_tf32(proj_w[idx]);
}
__global__ void abprep_kernel(const float* __restrict__ attention_biases,
                              const int* __restrict__ bias_idxs) {
    int idx = blockIdx.x * 256 + threadIdx.x;
    if (idx < NH * NPIX * NPIX) {
        int h = idx / (NPIX * NPIX);
        int nm = idx - h * (NPIX * NPIX);
        g_abmat[idx] = attention_biases[h * NPIX + bias_idxs[nm]];
    }
}
// per-(head,row) bias max; one warp per row
__global__ void abrmax_kernel() {
    int row = blockIdx.x * 8 + (threadIdx.x >> 5);   // 0..783
    int lane = threadIdx.x & 31;
    if (row >= NH * NPIX) return;
    const float* r = g_abmat + (size_t)row * NPIX;
    float mx = -1e30f;
    for (int m = lane; m < NPIX; m += 32) mx = fmaxf(mx, r[m]);
    #pragma unroll
    for (int off = 16; off; off >>= 1)
        mx = fmaxf(mx, __shfl_xor_sync(0xffffffffu, mx, off));
    if (lane == 0) g_abrmax[row] = mx;
}

// ---------------- proj kernel: mma.sync tf32 GEMM (unchanged) ----------------
#define PJ_NT 128
#define PJ_AS 36
#define PJ_A_FLOATS (256 * PJ_AS)
#define PJ_B_FLOATS (128 * PJ_AS)
#define PJ_BUF_FLOATS (PJ_A_FLOATS + PJ_B_FLOATS)
#define PJ_SMEM_BYTES (2 * PJ_BUF_FLOATS * 4)

__global__ void __launch_bounds__(256, 1)
proj_mma_kernel(const float* __restrict__ proj_scale,
                const float* __restrict__ proj_bias,
                float* __restrict__ out)
{
    extern __shared__ float smf[];
    const uint32_t smem_base = smem_u32(smf);

    const int tid  = threadIdx.x;
    const int wid  = tid >> 5;
    const int lane = tid & 31;
    const int g    = lane >> 2;
    const int tig  = lane & 3;
    const int n0   = blockIdx.x * PJ_NT;

    const int o0 = (wid & 3) * 64;
    const int nb = (wid >> 2) * 64;

    float acc[4][8][4];
    #pragma unroll
    for (int mi = 0; mi < 4; mi++)
        #pragma unroll
        for (int ni = 0; ni < 8; ni++)
            #pragma unroll
            for (int c = 0; c < 4; c++) acc[mi][ni][c] = 0.f;

    auto issue_chunk = [&](int c) {
        const int buf = c & 1;
        const int k0 = c * 32;
        const uint32_t abase = smem_base + (uint32_t)(buf * PJ_BUF_FLOATS) * 4u;
        const uint32_t bbase = abase + (uint32_t)PJ_A_FLOATS * 4u;
        #pragma unroll
        for (int it = 0; it < 8; it++) {
            int idx = it * 256 + tid;
            int row = idx >> 3, k4 = idx & 7;
            CP_ASYNC16(abase + (uint32_t)(row * PJ_AS + k4 * 4) * 4u,
                       g_wt + (size_t)row * 256 + k0 + k4 * 4);
        }
        #pragma unroll
        for (int it = 0; it < 4; it++) {
            int idx = it * 256 + tid;
            int row = idx >> 3, k4 = idx & 7;
            CP_ASYNC16(bbase + (uint32_t)(row * PJ_AS + k4 * 4) * 4u,
                       g_cat_t + (size_t)(n0 + row) * 256 + k0 + k4 * 4);
        }
        CP_COMMIT();
    };

    issue_chunk(0);

    for (int c = 0; c < 8; c++) {
        CP_WAIT0();
        __syncthreads();
        if (c < 7) issue_chunk(c + 1);

        const int buf = c & 1;
        const uint32_t* Asu = (const uint32_t*)(smf + buf * PJ_BUF_FLOATS);
        const uint32_t* Bsu = Asu + PJ_A_FLOATS;
        const int a_base = (o0 + g) * PJ_AS + tig;
        const int b_base = (nb + g) * PJ_AS + tig;

        #pragma unroll
        for (int k8 = 0; k8 < 32; k8 += 8) {
            uint32_t a[4][4];
            #pragma unroll
            for (int mi = 0; mi < 4; mi++) {
                int ab = a_base + mi * (16 * PJ_AS) + k8;
                a[mi][0] = Asu[ab];
                a[mi][1] = Asu[ab + 8 * PJ_AS];
                a[mi][2] = Asu[ab + 4];
                a[mi][3] = Asu[ab + 8 * PJ_AS + 4];
            }
            uint32_t bfr[8][2];
            #pragma unroll
            for (int ni = 0; ni < 8; ni++) {
                int bb = b_base + ni * (8 * PJ_AS) + k8;
                bfr[ni][0] = Bsu[bb];
                bfr[ni][1] = Bsu[bb + 4];
            }
            #pragma unroll
            for (int mi = 0; mi < 4; mi++)
                #pragma unroll
                for (int ni = 0; ni < 8; ni++)
                    mma_tf32(acc[mi][ni], a[mi], bfr[ni]);
        }
        __syncthreads();
    }

    float* Ssm = smf;
    #pragma unroll
    for (int h = 0; h < 2; h++) {
        __syncthreads();
        if ((wid >> 2) == h) {
            #pragma unroll
            for (int mi = 0; mi < 4; mi++) {
                int orow = o0 + mi * 16 + g;
                #pragma unroll
                for (int ni = 0; ni < 8; ni++) {
                    int nl = ni * 8 + 2 * tig;
                    *(float2*)&Ssm[orow * 68 + nl] =
                        make_float2(acc[mi][ni][0], acc[mi][ni][1]);
                    *(float2*)&Ssm[(orow + 8) * 68 + nl] =
                        make_float2(acc[mi][ni][2], acc[mi][ni][3]);
                }
            }
        }
        __syncthreads();
        #pragma unroll 4
        for (int it = 0; it < 64; it++) {
            int idx = it * 256 + tid;
            int o = idx >> 6, nn = idx & 63;
            float v = Ssm[o * 68 + nn];
            v = v * proj_scale[o] + proj_bias[o];
            unsigned ng = (unsigned)(n0 + h * 64 + nn);
            unsigned bb = ng / 196u;
            unsigned pp = ng - bb * 196u;
            out[(size_t)bb * (DIM * NPIX) + (size_t)o * NPIX + pp] = v;
        }
    }
}

extern "C" void kernel_launch(void* const* d_in, const int* in_sizes, int n_in,
                              void* d_out, int out_size)
{
    (void)in_sizes; (void)n_in; (void)out_size;
    const float* x          = (const float*)d_in[0];
    const float* qkv_w      = (const float*)d_in[1];
    const float* qkv_scale  = (const float*)d_in[2];
    const float* qkv_bias   = (const float*)d_in[3];
    const float* dw_w       = (const float*)d_in[4];
    const float* dw_scale   = (const float*)d_in[5];
    const float* dw_bias    = (const float*)d_in[6];
    const float* proj_w     = (const float*)d_in[7];
    const float* proj_scale = (const float*)d_in[8];
    const float* proj_bias  = (const float*)d_in[9];
    const float* attn_b     = (const float*)d_in[10];
    const int*   bias_idxs  = (const int*)d_in[11];
    float* out = (float*)d_out;

    cudaFuncSetAttribute(cascade_kernel, cudaFuncAttributeMaxDynamicSharedMemorySize, SMEM1_BYTES);
    cudaFuncSetAttribute(proj_mma_kernel, cudaFuncAttributeMaxDynamicSharedMemorySize, PJ_SMEM_BYTES);

    abprep_kernel<<<(NH * NPIX * NPIX + 255) / 256, 256>>>(attn_b, bias_idxs);
    abrmax_kernel<<<(NH * NPIX + 7) / 8, 256>>>();
    cascade_kernel<<<BATCH, 512, SMEM1_BYTES>>>(x, qkv_w, qkv_scale, qkv_bias,
                                                dw_w, dw_scale, dw_bias);
    wprep_kernel<<<DIM * DIM / 256, 256>>>(proj_w);
    proj_mma_kernel<<<(BATCH * NPIX) / PJ_NT, 256, PJ_SMEM_BYTES>>>(proj_scale, proj_bias, out);
}

// round 11
// speedup vs baseline: 1.3577x; 1.3577x over previous
#include <cuda_runtime.h>
#include <math.h>
#include <cstdint>

// ---------------- problem constants ----------------
#define BATCH 512
#define NH 4
#define KD 16
#define DD 64
#define DIM 256
#define QO 96
#define RESX 14
#define NPIX 196

typedef unsigned long long ull;

// global scratch
__device__ __align__(128) float g_cat_t[(size_t)BATCH * NPIX * DIM];
__device__ __align__(128) float g_wt[DIM * DIM];
__device__ __align__(128) float g_abmat[NH * NPIX * NPIX + 16];

__device__ __forceinline__ float to_tf32(float x) {
    float r; asm("cvt.rna.satfinite.tf32.f32 %0, %1;" : "=f"(r) : "f"(x)); return r;
}
__device__ __forceinline__ uint32_t smem_u32(const void* p) {
    uint32_t a;
    asm("{ .reg .u64 t; cvta.to.shared.u64 t, %1; cvt.u32.u64 %0, t; }" : "=r"(a) : "l"(p));
    return a;
}
// fragment-pack permutation: block of 8 cols -> pairs (j, j+4) adjacent
__device__ __forceinline__ int pidx(int m) {
    return (m & ~7) + ((m & 3) * 2) + ((m >> 2) & 1);
}

// ---------------- cp.async helpers ----------------
#define CP_ASYNC16(dst_u32, src_ptr) \
    asm volatile("cp.async.cg.shared.global [%0], [%1], 16;" :: "r"(dst_u32), "l"(src_ptr))
#define CP_COMMIT() asm volatile("cp.async.commit_group;" ::: "memory")
#define CP_WAIT0()  asm volatile("cp.async.wait_group 0;" ::: "memory")

// ---------------- mma.sync tf32 m16n8k8 ----------------
__device__ __forceinline__ void mma_tf32(float* d, const uint32_t* a, const uint32_t* b) {
    asm volatile(
        "mma.sync.aligned.m16n8k8.row.col.f32.tf32.tf32.f32 "
        "{%0,%1,%2,%3}, {%4,%5,%6,%7}, {%8,%9}, {%0,%1,%2,%3};"
        : "+f"(d[0]), "+f"(d[1]), "+f"(d[2]), "+f"(d[3])
        : "r"(a[0]), "r"(a[1]), "r"(a[2]), "r"(a[3]), "r"(b[0]), "r"(b[1]));
}
__device__ __forceinline__ void mma8(float* d, float a0, float a1, float a2, float a3,
                                     float b0, float b1) {
    uint32_t A[4] = {__float_as_uint(a0), __float_as_uint(a1),
                     __float_as_uint(a2), __float_as_uint(a3)};
    uint32_t B[2] = {__float_as_uint(b0), __float_as_uint(b1)};
    mma_tf32(d, A, B);
}

// ---------------- cascade smem layout (float offsets) ----------------
#define CF_FEAT 0            // 200 x 68
#define CF_QT   13600        // 224 x 18
#define CF_KT   17632        // 224 x 18
#define CF_QG   21664        // 224 x 18
#define CF_V    25696        // 64 x 200 packed
#define CF_WQ   38496        // 96 x 68
#define CF_QSC  45024
#define CF_QBI  45120
#define CF_DSC  45216
#define CF_DBI  45232
#define CF_DWW  45248
#define CF_END  45648
#define SMEM1_BYTES (CF_END * 4)      // 182592

__global__ void __launch_bounds__(512, 1)
cascade_kernel(const float* __restrict__ x,
               const float* __restrict__ qkv_w,
               const float* __restrict__ qkv_scale,
               const float* __restrict__ qkv_bias,
               const float* __restrict__ dw_w,
               const float* __restrict__ dw_scale,
               const float* __restrict__ dw_bias)
{
    extern __shared__ float sm[];
    float* featT = sm + CF_FEAT;
    float* qT    = sm + CF_QT;
    float* kT    = sm + CF_KT;
    float* qgT   = sm + CF_QG;
    float* vv    = sm + CF_V;
    float* wq    = sm + CF_WQ;
    float* qsc   = sm + CF_QSC;
    float* qbi   = sm + CF_QBI;
    float* dsc   = sm + CF_DSC;
    float* dbi   = sm + CF_DBI;
    float* dww   = sm + CF_DWW;

    const int b    = blockIdx.x;
    const int tid  = threadIdx.x;
    const int warp = tid >> 5;    // 0..15
    const int lane = tid & 31;
    const int g    = lane >> 2;   // 0..7
    const int tig  = lane & 3;    // 0..3

    // one-time zero padding
    for (int idx = tid; idx < 28 * 18; idx += 512) {
        qgT[196 * 18 + idx] = 0.f;
        kT[196 * 18 + idx] = 0.f;
    }
    if (tid < 4 * 68) featT[196 * 68 + tid] = 0.f;
    if (tid < 256) {
        int d = tid >> 2, s = tid & 3;
        vv[d * 200 + 193 + 2 * s] = 0.f;
    }
    __syncthreads();

    for (int i = 0; i < NH; i++) {
        // ---------- Phase A ----------
        {
            const float* xb = x + ((size_t)b * DIM + i * DD) * NPIX;
            if (i == 0) {
                for (int idx = tid; idx < DD * NPIX; idx += 512) {
                    int c = idx / NPIX, n = idx - c * NPIX;
                    featT[n * 68 + c] = to_tf32(xb[idx]);
                }
            } else {
                for (int idx = tid; idx < DD * NPIX; idx += 512) {
                    int c = idx / NPIX, n = idx - c * NPIX;
                    featT[n * 68 + c] = to_tf32(featT[n * 68 + c] + xb[idx]);
                }
            }
            for (int idx = tid; idx < QO * 64; idx += 512)
                wq[(idx >> 6) * 68 + (idx & 63)] = to_tf32(qkv_w[i * QO * 64 + idx]);
            if (tid < 400) dww[tid] = dw_w[i * 400 + tid];
            if (tid >= 400 && tid < 416) {
                int c = tid - 400;
                dsc[c] = dw_scale[i * KD + c]; dbi[c] = dw_bias[i * KD + c];
            }
            if (tid >= 416) {
                int o = tid - 416;
                qsc[o] = qkv_scale[i * QO + o]; qbi[o] = qkv_bias[i * QO + o];
            }
        }
        __syncthreads();

        // ---------- Phase B: QKV via mma, 75 (nt,mp) tasks over 16 warps ----------
        for (int t = warp; t < 75; t += 16) {
            const int nt = t / 3, mp = t - nt * 3;
            const int nb0 = nt * 8;
            float B0[8], B1[8];
            #pragma unroll
            for (int ks = 0; ks < 8; ks++) {
                B0[ks] = featT[(nb0 + g) * 68 + ks * 8 + tig];
                B1[ks] = featT[(nb0 + g) * 68 + ks * 8 + tig + 4];
            }
            const int oX = (2 * mp) * 16, oY = (2 * mp + 1) * 16;
            float dd0[4] = {0.f, 0.f, 0.f, 0.f};
            float dd1[4] = {0.f, 0.f, 0.f, 0.f};
            #pragma unroll
            for (int ks = 0; ks < 8; ks++) {
                mma8(dd0, wq[(oX + g) * 68 + ks * 8 + tig],
                          wq[(oX + g + 8) * 68 + ks * 8 + tig],
                          wq[(oX + g) * 68 + ks * 8 + tig + 4],
                          wq[(oX + g + 8) * 68 + ks * 8 + tig + 4],
                          B0[ks], B1[ks]);
                mma8(dd1, wq[(oY + g) * 68 + ks * 8 + tig],
                          wq[(oY + g + 8) * 68 + ks * 8 + tig],
                          wq[(oY + g) * 68 + ks * 8 + tig + 4],
                          wq[(oY + g + 8) * 68 + ks * 8 + tig + 4],
                          B0[ks], B1[ks]);
            }
            #pragma unroll
            for (int h = 0; h < 2; h++) {
                const int mt = 2 * mp + h;
                float* dd = h ? dd1 : dd0;
                const int oA = mt * 16 + g, oB = oA + 8;
                const float sA = qsc[oA], bA = qbi[oA];
                const float sB = qsc[oB], bB = qbi[oB];
                float y0 = dd[0] * sA + bA, y1 = dd[1] * sA + bA;
                float y2 = dd[2] * sB + bB, y3 = dd[3] * sB + bB;
                const int nc = nb0 + 2 * tig;
                if (mt == 0) {
                    qT[nc * 18 + oA] = y0; qT[(nc + 1) * 18 + oA] = y1;
                    qT[nc * 18 + oB] = y2; qT[(nc + 1) * 18 + oB] = y3;
                } else if (mt == 1) {
                    int c0 = oA - 16, c1 = oB - 16;
                    kT[nc * 18 + c0] = to_tf32(y0); kT[(nc + 1) * 18 + c0] = to_tf32(y1);
                    kT[nc * 18 + c1] = to_tf32(y2); kT[(nc + 1) * 18 + c1] = to_tf32(y3);
                } else {
                    int dA = oA - 32, dB = oB - 32;
                    if (nc < 196) {
                        vv[dA * 200 + pidx(nc)] = to_tf32(y0);
                        vv[dB * 200 + pidx(nc)] = to_tf32(y2);
                    }
                    if (nc + 1 < 196) {
                        vv[dA * 200 + pidx(nc + 1)] = to_tf32(y1);
                        vv[dB * 200 + pidx(nc + 1)] = to_tf32(y3);
                    }
                }
            }
        }
        __syncthreads();

        // ---------- Phase C ----------
        for (int t = tid; t < KD * NPIX; t += 512) {
            int n = t >> 4, c = t & 15;
            int py = n / RESX, px = n - py * RESX;
            float s = 0.f;
            #pragma unroll
            for (int dy = 0; dy < 5; dy++) {
                int yy = py + dy - 2;
                if (yy < 0 || yy >= RESX) continue;
                #pragma unroll
                for (int dx = 0; dx < 5; dx++) {
                    int xx = px + dx - 2;
                    if (xx < 0 || xx >= RESX) continue;
                    s += dww[c * 25 + dy * 5 + dx] * qT[(yy * RESX + xx) * 18 + c];
                }
            }
            float dq = s * dsc[c] + dbi[c];
            float gl = 0.5f * dq * (1.0f + erff(dq * 0.70710678118654752440f));
            qgT[n * 18 + c] = to_tf32(gl + qT[n * 18 + c]);
        }
        __syncthreads();

        // ---------- Phase D: warp-owned 16-row stripes, barrier-free ----------
        const float* abm = g_abmat + (size_t)i * (NPIX * NPIX);
        float* gcb = g_cat_t + ((size_t)b * NPIX) * DIM + i * DD;

        if (warp < 13) {
            const int r0 = warp * 16;
            float aq0 = qgT[(r0 + g) * 18 + tig],      aq1 = qgT[(r0 + g + 8) * 18 + tig];
            float aq2 = qgT[(r0 + g) * 18 + tig + 4],  aq3 = qgT[(r0 + g + 8) * 18 + tig + 4];
            float aq4 = qgT[(r0 + g) * 18 + tig + 8],  aq5 = qgT[(r0 + g + 8) * 18 + tig + 8];
            float aq6 = qgT[(r0 + g) * 18 + tig + 12], aq7 = qgT[(r0 + g + 8) * 18 + tig + 12];
            const int ngA = min(r0 + g, 195), ngB = min(r0 + g + 8, 195);
            const float* abrA = abm + (size_t)ngA * NPIX;
            const float* abrB = abm + (size_t)ngB * NPIX;
            const int m0l = 2 * tig;

            // pass 1: row max
            float Mg = -1e30f, Mg8 = -1e30f;
            #pragma unroll 5
            for (int nt = 0; nt < 25; nt++) {
                const int mm0 = nt * 8;
                float b00 = kT[(mm0 + g) * 18 + tig],     b01 = kT[(mm0 + g) * 18 + tig + 4];
                float b10 = kT[(mm0 + g) * 18 + tig + 8], b11 = kT[(mm0 + g) * 18 + tig + 12];
                float dd[4] = {0.f, 0.f, 0.f, 0.f};
                mma8(dd, aq0, aq1, aq2, aq3, b00, b01);
                mma8(dd, aq4, aq5, aq6, aq7, b10, b11);
                const int m0 = mm0 + m0l;
                float2 abA = *(const float2*)&abrA[m0];
                float2 abB = *(const float2*)&abrB[m0];
                float s00 = dd[0] * 0.25f + abA.x;
                float s01 = dd[1] * 0.25f + abA.y;
                float s10 = dd[2] * 0.25f + abB.x;
                float s11 = dd[3] * 0.25f + abB.y;
                if (m0 >= NPIX)     { s00 = -1e30f; s10 = -1e30f; }
                if (m0 + 1 >= NPIX) { s01 = -1e30f; s11 = -1e30f; }
                Mg  = fmaxf(Mg,  fmaxf(s00, s01));
                Mg8 = fmaxf(Mg8, fmaxf(s10, s11));
            }
            Mg  = fmaxf(Mg,  __shfl_xor_sync(0xffffffffu, Mg, 1));
            Mg  = fmaxf(Mg,  __shfl_xor_sync(0xffffffffu, Mg, 2));
            Mg8 = fmaxf(Mg8, __shfl_xor_sync(0xffffffffu, Mg8, 1));
            Mg8 = fmaxf(Mg8, __shfl_xor_sync(0xffffffffu, Mg8, 2));

            // pass 2: exp + AV
            float o[8][4];
            #pragma unroll
            for (int j = 0; j < 8; j++) { o[j][0] = o[j][1] = o[j][2] = o[j][3] = 0.f; }
            float lg = 0.f, lg8 = 0.f;
            const int srcA = (g << 2) | (tig >> 1);
            const int srcB = srcA + 2;
            const bool odd = (tig & 1);

            #pragma unroll 5
            for (int nt = 0; nt < 25; nt++) {
                const int mm0 = nt * 8;
                float b00 = kT[(mm0 + g) * 18 + tig],     b01 = kT[(mm0 + g) * 18 + tig + 4];
                float b10 = kT[(mm0 + g) * 18 + tig + 8], b11 = kT[(mm0 + g) * 18 + tig + 12];
                float dd[4] = {0.f, 0.f, 0.f, 0.f};
                mma8(dd, aq0, aq1, aq2, aq3, b00, b01);
                mma8(dd, aq4, aq5, aq6, aq7, b10, b11);
                const int m0 = mm0 + m0l;
                float2 abA = *(const float2*)&abrA[m0];
                float2 abB = *(const float2*)&abrB[m0];
                float s00 = dd[0] * 0.25f + abA.x;
                float s01 = dd[1] * 0.25f + abA.y;
                float s10 = dd[2] * 0.25f + abB.x;
                float s11 = dd[3] * 0.25f + abB.y;
                if (m0 >= NPIX)     { s00 = -1e30f; s10 = -1e30f; }
                if (m0 + 1 >= NPIX) { s01 = -1e30f; s11 = -1e30f; }
                float p00 = to_tf32(__expf(s00 - Mg));
                float p01 = to_tf32(__expf(s01 - Mg));
                float p10 = to_tf32(__expf(s10 - Mg8));
                float p11 = to_tf32(__expf(s11 - Mg8));
                lg  += p00 + p01;
                lg8 += p10 + p11;
                float t0 = __shfl_sync(0xffffffffu, p00, srcA);
                float t1 = __shfl_sync(0xffffffffu, p01, srcA);
                float a0 = odd ? t1 : t0;
                float u0 = __shfl_sync(0xffffffffu, p10, srcA);
                float u1 = __shfl_sync(0xffffffffu, p11, srcA);
                float a1 = odd ? u1 : u0;
                float t2 = __shfl_sync(0xffffffffu, p00, srcB);
                float t3 = __shfl_sync(0xffffffffu, p01, srcB);
                float a2 = odd ? t3 : t2;
                float u2 = __shfl_sync(0xffffffffu, p10, srcB);
                float u3 = __shfl_sync(0xffffffffu, p11, srcB);
                float a3 = odd ? u3 : u2;
                #pragma unroll
                for (int j = 0; j < 8; j++) {
                    float2 bv = *(const float2*)&vv[(j * 8 + g) * 200 + mm0 + m0l];
                    mma8(o[j], a0, a1, a2, a3, bv.x, bv.y);
                }
            }
            lg  += __shfl_xor_sync(0xffffffffu, lg, 1);
            lg  += __shfl_xor_sync(0xffffffffu, lg, 2);
            lg8 += __shfl_xor_sync(0xffffffffu, lg8, 1);
            lg8 += __shfl_xor_sync(0xffffffffu, lg8, 2);
            float ivg = 1.0f / lg, ivg8 = 1.0f / lg8;

            const int nA = r0 + g, nB = r0 + g + 8;
            #pragma unroll
            for (int j = 0; j < 8; j++) {
                const int dc = j * 8 + 2 * tig;
                if (nA < NPIX) {
                    float v0 = o[j][0] * ivg, v1 = o[j][1] * ivg;
                    *(float2*)&featT[nA * 68 + dc] = make_float2(v0, v1);
                    *(float2*)&gcb[(size_t)nA * DIM + dc] =
                        make_float2(to_tf32(fmaxf(v0, 0.f)), to_tf32(fmaxf(v1, 0.f)));
                }
                if (nB < NPIX) {
                    float v2 = o[j][2] * ivg8, v3 = o[j][3] * ivg8;
                    *(float2*)&featT[nB * 68 + dc] = make_float2(v2, v3);
                    *(float2*)&gcb[(size_t)nB * DIM + dc] =
                        make_float2(to_tf32(fmaxf(v2, 0.f)), to_tf32(fmaxf(v3, 0.f)));
                }
            }
        }
        __syncthreads();
    }
}

// ---------------- prep kernels ----------------
__global__ void wprep_kernel(const float* __restrict__ proj_w) {
    int idx = blockIdx.x * 256 + threadIdx.x;
    g_wt[idx] = to_tf32(proj_w[idx]);
}
__global__ void abprep_kernel(const float* __restrict__ attention_biases,
                              const int* __restrict__ bias_idxs) {
    int idx = blockIdx.x * 256 + threadIdx.x;
    if (idx < NH * NPIX * NPIX) {
        int h = idx / (NPIX * NPIX);
        int nm = idx - h * (NPIX * NPIX);
        g_abmat[idx] = attention_biases[h * NPIX + bias_idxs[nm]];
    }
}

// ---------------- proj kernel: mma.sync tf32 GEMM, 512 threads (4 warps/SMSP) ----------------
#define PJ_NT 128
#define PJ_AS 36
#define PJ_A_FLOATS (256 * PJ_AS)
#define PJ_B_FLOATS (128 * PJ_AS)
#define PJ_BUF_FLOATS (PJ_A_FLOATS + PJ_B_FLOATS)
#define PJ_SMEM_BYTES (2 * PJ_BUF_FLOATS * 4)

__global__ void __launch_bounds__(512, 1)
proj_mma_kernel(const float* __restrict__ proj_scale,
                const float* __restrict__ proj_bias,
                float* __restrict__ out)
{
    extern __shared__ float smf[];
    const uint32_t smem_base = smem_u32(smf);

    const int tid  = threadIdx.x;
    const int wid  = tid >> 5;        // 0..15
    const int lane = tid & 31;
    const int g    = lane >> 2;
    const int tig  = lane & 3;
    const int n0   = blockIdx.x * PJ_NT;

    const int o0 = (wid & 3) * 64;        // warp M offset (4 M groups)
    const int nb = (wid >> 2) * 32;       // warp N offset (4 N groups)

    float acc[4][4][4];
    #pragma unroll
    for (int mi = 0; mi < 4; mi++)
        #pragma unroll
        for (int ni = 0; ni < 4; ni++)
            #pragma unroll
            for (int c = 0; c < 4; c++) acc[mi][ni][c] = 0.f;

    auto issue_chunk = [&](int c) {
        const int buf = c & 1;
        const int k0 = c * 32;
        const uint32_t abase = smem_base + (uint32_t)(buf * PJ_BUF_FLOATS) * 4u;
        const uint32_t bbase = abase + (uint32_t)PJ_A_FLOATS * 4u;
        #pragma unroll
        for (int it = 0; it < 4; it++) {
            int idx = it * 512 + tid;          // 0..2047
            int row = idx >> 3, k4 = idx & 7;
            CP_ASYNC16(abase + (uint32_t)(row * PJ_AS + k4 * 4) * 4u,
                       g_wt + (size_t)row * 256 + k0 + k4 * 4);
        }
        #pragma unroll
        for (int it = 0; it < 2; it++) {
            int idx = it * 512 + tid;          // 0..1023
            int row = idx >> 3, k4 = idx & 7;
            CP_ASYNC16(bbase + (uint32_t)(row * PJ_AS + k4 * 4) * 4u,
                       g_cat_t + (size_t)(n0 + row) * 256 + k0 + k4 * 4);
        }
        CP_COMMIT();
    };

    issue_chunk(0);

    for (int c = 0; c < 8; c++) {
        CP_WAIT0();
        __syncthreads();
        if (c < 7) issue_chunk(c + 1);

        const int buf = c & 1;
        const uint32_t* Asu = (const uint32_t*)(smf + buf * PJ_BUF_FLOATS);
        const uint32_t* Bsu = Asu + PJ_A_FLOATS;
        const int a_base = (o0 + g) * PJ_AS + tig;
        const int b_base = (nb + g) * PJ_AS + tig;

        #pragma unroll
        for (int k8 = 0; k8 < 32; k8 += 8) {
            uint32_t a[4][4];
            #pragma unroll
            for (int mi = 0; mi < 4; mi++) {
                int ab = a_base + mi * (16 * PJ_AS) + k8;
                a[mi][0] = Asu[ab];
                a[mi][1] = Asu[ab + 8 * PJ_AS];
                a[mi][2] = Asu[ab + 4];
                a[mi][3] = Asu[ab + 8 * PJ_AS + 4];
            }
            uint32_t bfr[4][2];
            #pragma unroll
            for (int ni = 0; ni < 4; ni++) {
                int bb = b_base + ni * (8 * PJ_AS) + k8;
                bfr[ni][0] = Bsu[bb];
                bfr[ni][1] = Bsu[bb + 4];
            }
            #pragma unroll
            for (int mi = 0; mi < 4; mi++)
                #pragma unroll
                for (int ni = 0; ni < 4; ni++)
                    mma_tf32(acc[mi][ni], a[mi], bfr[ni]);
        }
        __syncthreads();
    }

    // epilogue: two N-halves through smem, coalesced stores
    float* Ssm = smf;
    #pragma unroll
    for (int h = 0; h < 2; h++) {
        __syncthreads();
        if ((wid >> 3) == h) {
            const int nloc = nb - h * 64;   // 0 or 32 within half
            #pragma unroll
            for (int mi = 0; mi < 4; mi++) {
                int orow = o0 + mi * 16 + g;
                #pragma unroll
                for (int ni = 0; ni < 4; ni++) {
                    int nl = nloc + ni * 8 + 2 * tig;
                    *(float2*)&Ssm[orow * 68 + nl] =
                        make_float2(acc[mi][ni][0], acc[mi][ni][1]);
                    *(float2*)&Ssm[(orow + 8) * 68 + nl] =
                        make_float2(acc[mi][ni][2], acc[mi][ni][3]);
                }
            }
        }
        __syncthreads();
        #pragma unroll 4
        for (int it = 0; it < 32; it++) {
            int idx = it * 512 + tid;
            int o = idx >> 6, nn = idx & 63;
            float v = Ssm[o * 68 + nn];
            v = v * proj_scale[o] + proj_bias[o];
            unsigned ng = (unsigned)(n0 + h * 64 + nn);
            unsigned bb = ng / 196u;
            unsigned pp = ng - bb * 196u;
            out[(size_t)bb * (DIM * NPIX) + (size_t)o * NPIX + pp] = v;
        }
    }
}

extern "C" void kernel_launch(void* const* d_in, const int* in_sizes, int n_in,
                              void* d_out, int out_size)
{
    (void)in_sizes; (void)n_in; (void)out_size;
    const float* x          = (const float*)d_in[0];
    const float* qkv_w      = (const float*)d_in[1];
    const float* qkv_scale  = (const float*)d_in[2];
    const float* qkv_bias   = (const float*)d_in[3];
    const float* dw_w       = (const float*)d_in[4];
    const float* dw_scale   = (const float*)d_in[5];
    const float* dw_bias    = (const float*)d_in[6];
    const float* proj_w     = (const float*)d_in[7];
    const float* proj_scale = (const float*)d_in[8];
    const float* proj_bias  = (const float*)d_in[9];
    const float* attn_b     = (const float*)d_in[10];
    const int*   bias_idxs  = (const int*)d_in[11];
    float* out = (float*)d_out;

    cudaFuncSetAttribute(cascade_kernel, cudaFuncAttributeMaxDynamicSharedMemorySize, SMEM1_BYTES);
    cudaFuncSetAttribute(proj_mma_kernel, cudaFuncAttributeMaxDynamicSharedMemorySize, PJ_SMEM_BYTES);

    abprep_kernel<<<(NH * NPIX * NPIX + 255) / 256, 256>>>(attn_b, bias_idxs);
    cascade_kernel<<<BATCH, 512, SMEM1_BYTES>>>(x, qkv_w, qkv_scale, qkv_bias,
                                                dw_w, dw_scale, dw_bias);
    wprep_kernel<<<DIM * DIM / 256, 256>>>(proj_w);
    proj_mma_kernel<<<(BATCH * NPIX) / PJ_NT, 512, PJ_SMEM_BYTES>>>(proj_scale, proj_bias, out);
}

// round 15
// speedup vs baseline: 1.3596x; 1.0014x over previous
#include <cuda_runtime.h>
#include <math.h>
#include <cstdint>

// ---------------- problem constants ----------------
#define BATCH 512
#define NH 4
#define KD 16
#define DD 64
#define DIM 256
#define QO 96
#define RESX 14
#define NPIX 196

typedef unsigned long long ull;

// global scratch
__device__ __align__(128) float g_cat_t[(size_t)BATCH * NPIX * DIM];
__device__ __align__(128) float g_wt[DIM * DIM];
__device__ __align__(128) float g_abmat[NH * NPIX * NPIX + 16];

__device__ __forceinline__ float to_tf32(float x) {
    float r; asm("cvt.rna.satfinite.tf32.f32 %0, %1;" : "=f"(r) : "f"(x)); return r;
}
__device__ __forceinline__ uint32_t smem_u32(const void* p) {
    uint32_t a;
    asm("{ .reg .u64 t; cvta.to.shared.u64 t, %1; cvt.u32.u64 %0, t; }" : "=r"(a) : "l"(p));
    return a;
}
// fragment-pack permutation: block of 8 cols -> pairs (j, j+4) adjacent
__device__ __forceinline__ int pidx(int m) {
    return (m & ~7) + ((m & 3) * 2) + ((m >> 2) & 1);
}

// ---------------- cp.async helpers ----------------
#define CP_ASYNC16(dst_u32, src_ptr) \
    asm volatile("cp.async.cg.shared.global [%0], [%1], 16;" :: "r"(dst_u32), "l"(src_ptr))
#define CP_COMMIT() asm volatile("cp.async.commit_group;" ::: "memory")
#define CP_WAITG(n) asm volatile("cp.async.wait_group %0;" :: "n"(n) : "memory")

// ---------------- mma.sync tf32 m16n8k8 ----------------
__device__ __forceinline__ void mma_tf32(float* d, const uint32_t* a, const uint32_t* b) {
    asm volatile(
        "mma.sync.aligned.m16n8k8.row.col.f32.tf32.tf32.f32 "
        "{%0,%1,%2,%3}, {%4,%5,%6,%7}, {%8,%9}, {%0,%1,%2,%3};"
        : "+f"(d[0]), "+f"(d[1]), "+f"(d[2]), "+f"(d[3])
        : "r"(a[0]), "r"(a[1]), "r"(a[2]), "r"(a[3]), "r"(b[0]), "r"(b[1]));
}
__device__ __forceinline__ void mma8(float* d, float a0, float a1, float a2, float a3,
                                     float b0, float b1) {
    uint32_t A[4] = {__float_as_uint(a0), __float_as_uint(a1),
                     __float_as_uint(a2), __float_as_uint(a3)};
    uint32_t B[2] = {__float_as_uint(b0), __float_as_uint(b1)};
    mma_tf32(d, A, B);
}

// ---------------- cascade smem layout (float offsets) ----------------
#define CF_FEAT 0            // 200 x 68
#define CF_QT   13600        // 224 x 18
#define CF_KT   17632        // 224 x 18
#define CF_QG   21664        // 224 x 18
#define CF_V    25696        // 64 x 200 packed
#define CF_WQ   38496        // 96 x 68
#define CF_QSC  45024
#define CF_QBI  45120
#define CF_DSC  45216
#define CF_DBI  45232
#define CF_DWW  45248
#define CF_END  45648
#define SMEM1_BYTES (CF_END * 4)      // 182592

__global__ void __launch_bounds__(512, 1)
cascade_kernel(const float* __restrict__ x,
               const float* __restrict__ qkv_w,
               const float* __restrict__ qkv_scale,
               const float* __restrict__ qkv_bias,
               const float* __restrict__ dw_w,
               const float* __restrict__ dw_scale,
               const float* __restrict__ dw_bias)
{
    extern __shared__ float sm[];
    float* featT = sm + CF_FEAT;
    float* qT    = sm + CF_QT;
    float* kT    = sm + CF_KT;
    float* qgT   = sm + CF_QG;
    float* vv    = sm + CF_V;
    float* wq    = sm + CF_WQ;
    float* qsc   = sm + CF_QSC;
    float* qbi   = sm + CF_QBI;
    float* dsc   = sm + CF_DSC;
    float* dbi   = sm + CF_DBI;
    float* dww   = sm + CF_DWW;

    const int b    = blockIdx.x;
    const int tid  = threadIdx.x;
    const int warp = tid >> 5;    // 0..15
    const int lane = tid & 31;
    const int g    = lane >> 2;   // 0..7
    const int tig  = lane & 3;    // 0..3

    // one-time zero padding + head-0 weight staging
    for (int idx = tid; idx < 28 * 18; idx += 512) {
        qgT[196 * 18 + idx] = 0.f;
        kT[196 * 18 + idx] = 0.f;
    }
    if (tid < 4 * 68) featT[196 * 68 + tid] = 0.f;
    if (tid < 256) {
        int d = tid >> 2, s = tid & 3;
        vv[d * 200 + 193 + 2 * s] = 0.f;
    }
    for (int idx = tid; idx < QO * 64; idx += 512)
        wq[(idx >> 6) * 68 + (idx & 63)] = to_tf32(qkv_w[idx]);
    if (tid < 400) dww[tid] = dw_w[tid];
    if (tid >= 400 && tid < 416) {
        int c = tid - 400;
        dsc[c] = dw_scale[c]; dbi[c] = dw_bias[c];
    }
    if (tid >= 416) {
        int o = tid - 416;
        qsc[o] = qkv_scale[o]; qbi[o] = qkv_bias[o];
    }
    __syncthreads();

    for (int i = 0; i < NH; i++) {
        // ---------- Phase A: feat accumulate only ----------
        {
            const float* xb = x + ((size_t)b * DIM + i * DD) * NPIX;
            if (i == 0) {
                for (int idx = tid; idx < DD * NPIX; idx += 512) {
                    int c = idx / NPIX, n = idx - c * NPIX;
                    featT[n * 68 + c] = to_tf32(xb[idx]);
                }
            } else {
                for (int idx = tid; idx < DD * NPIX; idx += 512) {
                    int c = idx / NPIX, n = idx - c * NPIX;
                    featT[n * 68 + c] = to_tf32(featT[n * 68 + c] + xb[idx]);
                }
            }
        }
        __syncthreads();

        // ---------- Phase B: QKV via mma, 75 (nt,mp) tasks over 16 warps ----------
        for (int t = warp; t < 75; t += 16) {
            const int nt = t / 3, mp = t - nt * 3;
            const int nb0 = nt * 8;
            float B0[8], B1[8];
            #pragma unroll
            for (int ks = 0; ks < 8; ks++) {
                B0[ks] = featT[(nb0 + g) * 68 + ks * 8 + tig];
                B1[ks] = featT[(nb0 + g) * 68 + ks * 8 + tig + 4];
            }
            const int oX = (2 * mp) * 16, oY = (2 * mp + 1) * 16;
            float dd0[4] = {0.f, 0.f, 0.f, 0.f};
            float dd1[4] = {0.f, 0.f, 0.f, 0.f};
            #pragma unroll
            for (int ks = 0; ks < 8; ks++) {
                mma8(dd0, wq[(oX + g) * 68 + ks * 8 + tig],
                          wq[(oX + g + 8) * 68 + ks * 8 + tig],
                          wq[(oX + g) * 68 + ks * 8 + tig + 4],
                          wq[(oX + g + 8) * 68 + ks * 8 + tig + 4],
                          B0[ks], B1[ks]);
                mma8(dd1, wq[(oY + g) * 68 + ks * 8 + tig],
                          wq[(oY + g + 8) * 68 + ks * 8 + tig],
                          wq[(oY + g) * 68 + ks * 8 + tig + 4],
                          wq[(oY + g + 8) * 68 + ks * 8 + tig + 4],
                          B0[ks], B1[ks]);
            }
            #pragma unroll
            for (int h = 0; h < 2; h++) {
                const int mt = 2 * mp + h;
                float* dd = h ? dd1 : dd0;
                const int oA = mt * 16 + g, oB = oA + 8;
                const float sA = qsc[oA], bA = qbi[oA];
                const float sB = qsc[oB], bB = qbi[oB];
                float y0 = dd[0] * sA + bA, y1 = dd[1] * sA + bA;
                float y2 = dd[2] * sB + bB, y3 = dd[3] * sB + bB;
                const int nc = nb0 + 2 * tig;
                if (mt == 0) {
                    qT[nc * 18 + oA] = y0; qT[(nc + 1) * 18 + oA] = y1;
                    qT[nc * 18 + oB] = y2; qT[(nc + 1) * 18 + oB] = y3;
                } else if (mt == 1) {
                    int c0 = oA - 16, c1 = oB - 16;
                    kT[nc * 18 + c0] = to_tf32(y0); kT[(nc + 1) * 18 + c0] = to_tf32(y1);
                    kT[nc * 18 + c1] = to_tf32(y2); kT[(nc + 1) * 18 + c1] = to_tf32(y3);
                } else {
                    int dA = oA - 32, dB = oB - 32;
                    if (nc < 196) {
                        vv[dA * 200 + pidx(nc)] = to_tf32(y0);
                        vv[dB * 200 + pidx(nc)] = to_tf32(y2);
                    }
                    if (nc + 1 < 196) {
                        vv[dA * 200 + pidx(nc + 1)] = to_tf32(y1);
                        vv[dB * 200 + pidx(nc + 1)] = to_tf32(y3);
                    }
                }
            }
        }
        __syncthreads();

        // ---------- Phase C ----------
        for (int t = tid; t < KD * NPIX; t += 512) {
            int n = t >> 4, c = t & 15;
            int py = n / RESX, px = n - py * RESX;
            float s = 0.f;
            #pragma unroll
            for (int dy = 0; dy < 5; dy++) {
                int yy = py + dy - 2;
                if (yy < 0 || yy >= RESX) continue;
                #pragma unroll
                for (int dx = 0; dx < 5; dx++) {
                    int xx = px + dx - 2;
                    if (xx < 0 || xx >= RESX) continue;
                    s += dww[c * 25 + dy * 5 + dx] * qT[(yy * RESX + xx) * 18 + c];
                }
            }
            float dq = s * dsc[c] + dbi[c];
            float gl = 0.5f * dq * (1.0f + erff(dq * 0.70710678118654752440f));
            qgT[n * 18 + c] = to_tf32(gl + qT[n * 18 + c]);
        }
        __syncthreads();

        // ---------- Phase D: warp-owned 16-row stripes (warps 0-12);
        //            warps 13-15 prefetch next head's weights ----------
        const float* abm = g_abmat + (size_t)i * (NPIX * NPIX);
        float* gcb = g_cat_t + ((size_t)b * NPIX) * DIM + i * DD;

        if (warp < 13) {
            const int r0 = warp * 16;
            float aq0 = qgT[(r0 + g) * 18 + tig],      aq1 = qgT[(r0 + g + 8) * 18 + tig];
            float aq2 = qgT[(r0 + g) * 18 + tig + 4],  aq3 = qgT[(r0 + g + 8) * 18 + tig + 4];
            float aq4 = qgT[(r0 + g) * 18 + tig + 8],  aq5 = qgT[(r0 + g + 8) * 18 + tig + 8];
            float aq6 = qgT[(r0 + g) * 18 + tig + 12], aq7 = qgT[(r0 + g + 8) * 18 + tig + 12];
            const int ngA = min(r0 + g, 195), ngB = min(r0 + g + 8, 195);
            const float* abrA = abm + (size_t)ngA * NPIX;
            const float* abrB = abm + (size_t)ngB * NPIX;
            const int m0l = 2 * tig;

            // pass 1: row max
            float Mg = -1e30f, Mg8 = -1e30f;
            #pragma unroll 5
            for (int nt = 0; nt < 25; nt++) {
                const int mm0 = nt * 8;
                float b00 = kT[(mm0 + g) * 18 + tig],     b01 = kT[(mm0 + g) * 18 + tig + 4];
                float b10 = kT[(mm0 + g) * 18 + tig + 8], b11 = kT[(mm0 + g) * 18 + tig + 12];
                float dd[4] = {0.f, 0.f, 0.f, 0.f};
                mma8(dd, aq0, aq1, aq2, aq3, b00, b01);
                mma8(dd, aq4, aq5, aq6, aq7, b10, b11);
                const int m0 = mm0 + m0l;
                float2 abA = *(const float2*)&abrA[m0];
                float2 abB = *(const float2*)&abrB[m0];
                float s00 = dd[0] * 0.25f + abA.x;
                float s01 = dd[1] * 0.25f + abA.y;
                float s10 = dd[2] * 0.25f + abB.x;
                float s11 = dd[3] * 0.25f + abB.y;
                if (m0 >= NPIX)     { s00 = -1e30f; s10 = -1e30f; }
                if (m0 + 1 >= NPIX) { s01 = -1e30f; s11 = -1e30f; }
                Mg  = fmaxf(Mg,  fmaxf(s00, s01));
                Mg8 = fmaxf(Mg8, fmaxf(s10, s11));
            }
            Mg  = fmaxf(Mg,  __shfl_xor_sync(0xffffffffu, Mg, 1));
            Mg  = fmaxf(Mg,  __shfl_xor_sync(0xffffffffu, Mg, 2));
            Mg8 = fmaxf(Mg8, __shfl_xor_sync(0xffffffffu, Mg8, 1));
            Mg8 = fmaxf(Mg8, __shfl_xor_sync(0xffffffffu, Mg8, 2));

            // pass 2: exp + AV
            float o[8][4];
            #pragma unroll
            for (int j = 0; j < 8; j++) { o[j][0] = o[j][1] = o[j][2] = o[j][3] = 0.f; }
            float lg = 0.f, lg8 = 0.f;
            const int srcA = (g << 2) | (tig >> 1);
            const int srcB = srcA + 2;
            const bool odd = (tig & 1);

            #pragma unroll 5
            for (int nt = 0; nt < 25; nt++) {
                const int mm0 = nt * 8;
                float b00 = kT[(mm0 + g) * 18 + tig],     b01 = kT[(mm0 + g) * 18 + tig + 4];
                float b10 = kT[(mm0 + g) * 18 + tig + 8], b11 = kT[(mm0 + g) * 18 + tig + 12];
                float dd[4] = {0.f, 0.f, 0.f, 0.f};
                mma8(dd, aq0, aq1, aq2, aq3, b00, b01);
                mma8(dd, aq4, aq5, aq6, aq7, b10, b11);
                const int m0 = mm0 + m0l;
                float2 abA = *(const float2*)&abrA[m0];
                float2 abB = *(const float2*)&abrB[m0];
                float s00 = dd[0] * 0.25f + abA.x;
                float s01 = dd[1] * 0.25f + abA.y;
                float s10 = dd[2] * 0.25f + abB.x;
                float s11 = dd[3] * 0.25f + abB.y;
                if (m0 >= NPIX)     { s00 = -1e30f; s10 = -1e30f; }
                if (m0 + 1 >= NPIX) { s01 = -1e30f; s11 = -1e30f; }
                float p00 = to_tf32(__expf(s00 - Mg));
                float p01 = to_tf32(__expf(s01 - Mg));
                float p10 = to_tf32(__expf(s10 - Mg8));
                float p11 = to_tf32(__expf(s11 - Mg8));
                lg  += p00 + p01;
                lg8 += p10 + p11;
                float t0 = __shfl_sync(0xffffffffu, p00, srcA);
                float t1 = __shfl_sync(0xffffffffu, p01, srcA);
                float a0 = odd ? t1 : t0;
                float u0 = __shfl_sync(0xffffffffu, p10, srcA);
                float u1 = __shfl_sync(0xffffffffu, p11, srcA);
                float a1 = odd ? u1 : u0;
                float t2 = __shfl_sync(0xffffffffu, p00, srcB);
                float t3 = __shfl_sync(0xffffffffu, p01, srcB);
                float a2 = odd ? t3 : t2;
                float u2 = __shfl_sync(0xffffffffu, p10, srcB);
                float u3 = __shfl_sync(0xffffffffu, p11, srcB);
                float a3 = odd ? u3 : u2;
                #pragma unroll
                for (int j = 0; j < 8; j++) {
                    float2 bv = *(const float2*)&vv[(j * 8 + g) * 200 + mm0 + m0l];
                    mma8(o[j], a0, a1, a2, a3, bv.x, bv.y);
                }
            }
            lg  += __shfl_xor_sync(0xffffffffu, lg, 1);
            lg  += __shfl_xor_sync(0xffffffffu, lg, 2);
            lg8 += __shfl_xor_sync(0xffffffffu, lg8, 1);
            lg8 += __shfl_xor_sync(0xffffffffu, lg8, 2);
            float ivg = 1.0f / lg, ivg8 = 1.0f / lg8;

            const int nA = r0 + g, nB = r0 + g + 8;
            #pragma unroll
            for (int j = 0; j < 8; j++) {
                const int dc = j * 8 + 2 * tig;
                if (nA < NPIX) {
                    float v0 = o[j][0] * ivg, v1 = o[j][1] * ivg;
                    *(float2*)&featT[nA * 68 + dc] = make_float2(v0, v1);
                    *(float2*)&gcb[(size_t)nA * DIM + dc] =
                        make_float2(to_tf32(fmaxf(v0, 0.f)), to_tf32(fmaxf(v1, 0.f)));
                }
                if (nB < NPIX) {
                    float v2 = o[j][2] * ivg8, v3 = o[j][3] * ivg8;
                    *(float2*)&featT[nB * 68 + dc] = make_float2(v2, v3);
                    *(float2*)&gcb[(size_t)nB * DIM + dc] =
                        make_float2(to_tf32(fmaxf(v2, 0.f)), to_tf32(fmaxf(v3, 0.f)));
                }
            }
        } else if (i + 1 < NH) {
            // warps 13-15: stage next head's weights (regions unused during Phase D)
            const int t96 = (warp - 13) * 32 + lane;   // 0..95
            const int ih = i + 1;
            for (int idx = t96; idx < QO * 64; idx += 96)
                wq[(idx >> 6) * 68 + (idx & 63)] = to_tf32(qkv_w[ih * QO * 64 + idx]);
            for (int idx = t96; idx < 400; idx += 96)
                dww[idx] = dw_w[ih * 400 + idx];
            if (t96 < 16) {
                dsc[t96] = dw_scale[ih * KD + t96];
                dbi[t96] = dw_bias[ih * KD + t96];
            }
            for (int o = t96; o < QO; o += 96) {       // full coverage (bug fix)
                qsc[o] = qkv_scale[ih * QO + o];
                qbi[o] = qkv_bias[ih * QO + o];
            }
        }
        __syncthreads();
    }
}

// ---------------- prep kernels ----------------
__global__ void wprep_kernel(const float* __restrict__ proj_w) {
    int idx = blockIdx.x * 256 + threadIdx.x;
    g_wt[idx] = to_tf32(proj_w[idx]);
}
__global__ void abprep_kernel(const float* __restrict__ attention_biases,
                              const int* __restrict__ bias_idxs) {
    int idx = blockIdx.x * 256 + threadIdx.x;
    if (idx < NH * NPIX * NPIX) {
        int h = idx / (NPIX * NPIX);
        int nm = idx - h * (NPIX * NPIX);
        g_abmat[idx] = attention_biases[h * NPIX + bias_idxs[nm]];
    }
}

// ---------------- proj kernel: tf32 GEMM, 512 threads, 3-stage cp.async pipeline ----------------
#define PJ_NT 128
#define PJ_AS 36
#define PJ_A_FLOATS (256 * PJ_AS)
#define PJ_B_FLOATS (128 * PJ_AS)
#define PJ_BUF_FLOATS (PJ_A_FLOATS + PJ_B_FLOATS)
#define PJ_STAGES 3
#define PJ_SMEM_BYTES (PJ_STAGES * PJ_BUF_FLOATS * 4)   // 165888

__global__ void __launch_bounds__(512, 1)
proj_mma_kernel(const float* __restrict__ proj_scale,
                const float* __restrict__ proj_bias,
                float* __restrict__ out)
{
    extern __shared__ float smf[];
    const uint32_t smem_base = smem_u32(smf);

    const int tid  = threadIdx.x;
    const int wid  = tid >> 5;        // 0..15
    const int lane = tid & 31;
    const int g    = lane >> 2;
    const int tig  = lane & 3;
    const int n0   = blockIdx.x * PJ_NT;

    const int o0 = (wid & 3) * 64;        // warp M offset
    const int nb = (wid >> 2) * 32;       // warp N offset

    float acc[4][4][4];
    #pragma unroll
    for (int mi = 0; mi < 4; mi++)
        #pragma unroll
        for (int ni = 0; ni < 4; ni++)
            #pragma unroll
            for (int c = 0; c < 4; c++) acc[mi][ni][c] = 0.f;

    auto issue_chunk = [&](int c) {
        const int buf = c % PJ_STAGES;
        const int k0 = c * 32;
        const uint32_t abase = smem_base + (uint32_t)(buf * PJ_BUF_FLOATS) * 4u;
        const uint32_t bbase = abase + (uint32_t)PJ_A_FLOATS * 4u;
        #pragma unroll
        for (int it = 0; it < 4; it++) {
            int idx = it * 512 + tid;          // 0..2047
            int row = idx >> 3, k4 = idx & 7;
            CP_ASYNC16(abase + (uint32_t)(row * PJ_AS + k4 * 4) * 4u,
                       g_wt + (size_t)row * 256 + k0 + k4 * 4);
        }
        #pragma unroll
        for (int it = 0; it < 2; it++) {
            int idx = it * 512 + tid;          // 0..1023
            int row = idx >> 3, k4 = idx & 7;
            CP_ASYNC16(bbase + (uint32_t)(row * PJ_AS + k4 * 4) * 4u,
                       g_cat_t + (size_t)(n0 + row) * 256 + k0 + k4 * 4);
        }
        CP_COMMIT();
    };

    issue_chunk(0);
    issue_chunk(1);

    for (int c = 0; c < 8; c++) {
        if (c + 2 < 8) issue_chunk(c + 2);
        // guarantee chunk c resident: pending groups = c..min(c+2,7)
        if (c <= 5)      CP_WAITG(2);
        else if (c == 6) CP_WAITG(1);
        else             CP_WAITG(0);
        __syncthreads();

        const int buf = c % PJ_STAGES;
        const uint32_t* Asu = (const uint32_t*)(smf + buf * PJ_BUF_FLOATS);
        const uint32_t* Bsu = Asu + PJ_A_FLOATS;
        const int a_base = (o0 + g) * PJ_AS + tig;
        const int b_base = (nb + g) * PJ_AS + tig;

        #pragma unroll
        for (int k8 = 0; k8 < 32; k8 += 8) {
            uint32_t a[4][4];
            #pragma unroll
            for (int mi = 0; mi < 4; mi++) {
                int ab = a_base + mi * (16 * PJ_AS) + k8;
                a[mi][0] = Asu[ab];
                a[mi][1] = Asu[ab + 8 * PJ_AS];
                a[mi][2] = Asu[ab + 4];
                a[mi][3] = Asu[ab + 8 * PJ_AS + 4];
            }
            uint32_t bfr[4][2];
            #pragma unroll
            for (int ni = 0; ni < 4; ni++) {
                int bb = b_base + ni * (8 * PJ_AS) + k8;
                bfr[ni][0] = Bsu[bb];
                bfr[ni][1] = Bsu[bb + 4];
            }
            #pragma unroll
            for (int mi = 0; mi < 4; mi++)
                #pragma unroll
                for (int ni = 0; ni < 4; ni++)
                    mma_tf32(acc[mi][ni], a[mi], bfr[ni]);
        }
        __syncthreads();
    }

    // epilogue: two N-halves through smem, coalesced stores
    float* Ssm = smf;
    #pragma unroll
    for (int h = 0; h < 2; h++) {
        __syncthreads();
        if ((wid >> 3) == h) {
            const int nloc = nb - h * 64;   // 0 or 32 within half
            #pragma unroll
            for (int mi = 0; mi < 4; mi++) {
                int orow = o0 + mi * 16 + g;
                #pragma unroll
                for (int ni = 0; ni < 4; ni++) {
                    int nl = nloc + ni * 8 + 2 * tig;
                    *(float2*)&Ssm[orow * 68 + nl] =
                        make_float2(acc[mi][ni][0], acc[mi][ni][1]);
                    *(float2*)&Ssm[(orow + 8) * 68 + nl] =
                        make_float2(acc[mi][ni][2], acc[mi][ni][3]);
                }
            }
        }
        __syncthreads();
        #pragma unroll 4
        for (int it = 0; it < 32; it++) {
            int idx = it * 512 + tid;
            int o = idx >> 6, nn = idx & 63;
            float v = Ssm[o * 68 + nn];
            v = v * proj_scale[o] + proj_bias[o];
            unsigned ng = (unsigned)(n0 + h * 64 + nn);
            unsigned bb = ng / 196u;
            unsigned pp = ng - bb * 196u;
            out[(size_t)bb * (DIM * NPIX) + (size_t)o * NPIX + pp] = v;
        }
    }
}

extern "C" void kernel_launch(void* const* d_in, const int* in_sizes, int n_in,
                              void* d_out, int out_size)
{
    (void)in_sizes; (void)n_in; (void)out_size;
    const float* x          = (const float*)d_in[0];
    const float* qkv_w      = (const float*)d_in[1];
    const float* qkv_scale  = (const float*)d_in[2];
    const float* qkv_bias   = (const float*)d_in[3];
    const float* dw_w       = (const float*)d_in[4];
    const float* dw_scale   = (const float*)d_in[5];
    const float* dw_bias    = (const float*)d_in[6];
    const float* proj_w     = (const float*)d_in[7];
    const float* proj_scale = (const float*)d_in[8];
    const float* proj_bias  = (const float*)d_in[9];
    const float* attn_b     = (const float*)d_in[10];
    const int*   bias_idxs  = (const int*)d_in[11];
    float* out = (float*)d_out;

    cudaFuncSetAttribute(cascade_kernel, cudaFuncAttributeMaxDynamicSharedMemorySize, SMEM1_BYTES);
    cudaFuncSetAttribute(proj_mma_kernel, cudaFuncAttributeMaxDynamicSharedMemorySize, PJ_SMEM_BYTES);

    abprep_kernel<<<(NH * NPIX * NPIX + 255) / 256, 256>>>(attn_b, bias_idxs);
    cascade_kernel<<<BATCH, 512, SMEM1_BYTES>>>(x, qkv_w, qkv_scale, qkv_bias,
                                                dw_w, dw_scale, dw_bias);
    wprep_kernel<<<DIM * DIM / 256, 256>>>(proj_w);
    proj_mma_kernel<<<(BATCH * NPIX) / PJ_NT, 512, PJ_SMEM_BYTES>>>(proj_scale, proj_bias, out);
}

// round 17
// speedup vs baseline: 1.3629x; 1.0024x over previous
#include <cuda_runtime.h>
#include <math.h>
#include <cstdint>

// ---------------- problem constants ----------------
#define BATCH 512
#define NH 4
#define KD 16
#define DD 64
#define DIM 256
#define QO 96
#define RESX 14
#define NPIX 196

typedef unsigned long long ull;

// global scratch
__device__ __align__(128) float g_cat_t[(size_t)BATCH * NPIX * DIM];
__device__ __align__(128) float g_wt[DIM * DIM];
__device__ __align__(128) float g_abmat[NH * NPIX * NPIX + 16];

__device__ __forceinline__ float to_tf32(float x) {
    float r; asm("cvt.rna.satfinite.tf32.f32 %0, %1;" : "=f"(r) : "f"(x)); return r;
}
__device__ __forceinline__ uint32_t smem_u32(const void* p) {
    uint32_t a;
    asm("{ .reg .u64 t; cvta.to.shared.u64 t, %1; cvt.u32.u64 %0, t; }" : "=r"(a) : "l"(p));
    return a;
}
// fragment-pack permutation: block of 8 cols -> pairs (j, j+4) adjacent
__device__ __forceinline__ int pidx(int m) {
    return (m & ~7) + ((m & 3) * 2) + ((m >> 2) & 1);
}

// ---------------- cp.async helpers ----------------
#define CP_ASYNC16(dst_u32, src_ptr) \
    asm volatile("cp.async.cg.shared.global [%0], [%1], 16;" :: "r"(dst_u32), "l"(src_ptr))
#define CP_COMMIT() asm volatile("cp.async.commit_group;" ::: "memory")
#define CP_WAITG(n) asm volatile("cp.async.wait_group %0;" :: "n"(n) : "memory")

// ---------------- mma.sync tf32 m16n8k8 ----------------
__device__ __forceinline__ void mma_tf32(float* d, const uint32_t* a, const uint32_t* b) {
    asm volatile(
        "mma.sync.aligned.m16n8k8.row.col.f32.tf32.tf32.f32 "
        "{%0,%1,%2,%3}, {%4,%5,%6,%7}, {%8,%9}, {%0,%1,%2,%3};"
        : "+f"(d[0]), "+f"(d[1]), "+f"(d[2]), "+f"(d[3])
        : "r"(a[0]), "r"(a[1]), "r"(a[2]), "r"(a[3]), "r"(b[0]), "r"(b[1]));
}
__device__ __forceinline__ void mma8(float* d, float a0, float a1, float a2, float a3,
                                     float b0, float b1) {
    uint32_t A[4] = {__float_as_uint(a0), __float_as_uint(a1),
                     __float_as_uint(a2), __float_as_uint(a3)};
    uint32_t B[2] = {__float_as_uint(b0), __float_as_uint(b1)};
    mma_tf32(d, A, B);
}

// ---------------- cascade smem layout (float offsets) ----------------
#define CF_FEAT 0            // 200 x 68
#define CF_QT   13600        // 224 x 18
#define CF_KT   17632        // 224 x 18
#define CF_QG   21664        // 224 x 18
#define CF_V    25696        // 64 x 200 packed
#define CF_WQ   38496        // 96 x 68
#define CF_QSC  45024
#define CF_QBI  45120
#define CF_DSC  45216
#define CF_DBI  45232
#define CF_DWW  45248
#define CF_END  45648
#define SMEM1_BYTES (CF_END * 4)      // 182592

__global__ void __launch_bounds__(512, 1)
cascade_kernel(const float* __restrict__ x,
               const float* __restrict__ qkv_w,
               const float* __restrict__ qkv_scale,
               const float* __restrict__ qkv_bias,
               const float* __restrict__ dw_w,
               const float* __restrict__ dw_scale,
               const float* __restrict__ dw_bias)
{
    extern __shared__ float sm[];
    float* featT = sm + CF_FEAT;
    float* qT    = sm + CF_QT;
    float* kT    = sm + CF_KT;
    float* qgT   = sm + CF_QG;
    float* vv    = sm + CF_V;
    float* wq    = sm + CF_WQ;
    float* qsc   = sm + CF_QSC;
    float* qbi   = sm + CF_QBI;
    float* dsc   = sm + CF_DSC;
    float* dbi   = sm + CF_DBI;
    float* dww   = sm + CF_DWW;

    const int b    = blockIdx.x;
    const int tid  = threadIdx.x;
    const int warp = tid >> 5;    // 0..15
    const int lane = tid & 31;
    const int g    = lane >> 2;   // 0..7
    const int tig  = lane & 3;    // 0..3

    // one-time zero padding + head-0 weight staging
    for (int idx = tid; idx < 28 * 18; idx += 512) {
        qgT[196 * 18 + idx] = 0.f;
        kT[196 * 18 + idx] = 0.f;
    }
    if (tid < 4 * 68) featT[196 * 68 + tid] = 0.f;
    if (tid < 256) {
        int d = tid >> 2, s = tid & 3;
        vv[d * 200 + 193 + 2 * s] = 0.f;
    }
    for (int idx = tid; idx < QO * 64; idx += 512)
        wq[(idx >> 6) * 68 + (idx & 63)] = to_tf32(qkv_w[idx]);
    if (tid < 400) dww[tid] = dw_w[tid];
    if (tid >= 400 && tid < 416) {
        int c = tid - 400;
        dsc[c] = dw_scale[c]; dbi[c] = dw_bias[c];
    }
    if (tid >= 416) {
        int o = tid - 416;
        qsc[o] = qkv_scale[o]; qbi[o] = qkv_bias[o];
    }
    __syncthreads();

    for (int i = 0; i < NH; i++) {
        // ---------- Phase A: feat accumulate only ----------
        {
            const float* xb = x + ((size_t)b * DIM + i * DD) * NPIX;
            if (i == 0) {
                for (int idx = tid; idx < DD * NPIX; idx += 512) {
                    int c = idx / NPIX, n = idx - c * NPIX;
                    featT[n * 68 + c] = to_tf32(xb[idx]);
                }
            } else {
                for (int idx = tid; idx < DD * NPIX; idx += 512) {
                    int c = idx / NPIX, n = idx - c * NPIX;
                    featT[n * 68 + c] = to_tf32(featT[n * 68 + c] + xb[idx]);
                }
            }
        }
        __syncthreads();

        // ---------- Phase B: QKV via mma, 75 (nt,mp) tasks over 16 warps ----------
        for (int t = warp; t < 75; t += 16) {
            const int nt = t / 3, mp = t - nt * 3;
            const int nb0 = nt * 8;
            float B0[8], B1[8];
            #pragma unroll
            for (int ks = 0; ks < 8; ks++) {
                B0[ks] = featT[(nb0 + g) * 68 + ks * 8 + tig];
                B1[ks] = featT[(nb0 + g) * 68 + ks * 8 + tig + 4];
            }
            const int oX = (2 * mp) * 16, oY = (2 * mp + 1) * 16;
            float dd0[4] = {0.f, 0.f, 0.f, 0.f};
            float dd1[4] = {0.f, 0.f, 0.f, 0.f};
            #pragma unroll
            for (int ks = 0; ks < 8; ks++) {
                mma8(dd0, wq[(oX + g) * 68 + ks * 8 + tig],
                          wq[(oX + g + 8) * 68 + ks * 8 + tig],
                          wq[(oX + g) * 68 + ks * 8 + tig + 4],
                          wq[(oX + g + 8) * 68 + ks * 8 + tig + 4],
                          B0[ks], B1[ks]);
                mma8(dd1, wq[(oY + g) * 68 + ks * 8 + tig],
                          wq[(oY + g + 8) * 68 + ks * 8 + tig],
                          wq[(oY + g) * 68 + ks * 8 + tig + 4],
                          wq[(oY + g + 8) * 68 + ks * 8 + tig + 4],
                          B0[ks], B1[ks]);
            }
            #pragma unroll
            for (int h = 0; h < 2; h++) {
                const int mt = 2 * mp + h;
                float* dd = h ? dd1 : dd0;
                const int oA = mt * 16 + g, oB = oA + 8;
                const float sA = qsc[oA], bA = qbi[oA];
                const float sB = qsc[oB], bB = qbi[oB];
                float y0 = dd[0] * sA + bA, y1 = dd[1] * sA + bA;
                float y2 = dd[2] * sB + bB, y3 = dd[3] * sB + bB;
                const int nc = nb0 + 2 * tig;
                if (mt == 0) {
                    qT[nc * 18 + oA] = y0; qT[(nc + 1) * 18 + oA] = y1;
                    qT[nc * 18 + oB] = y2; qT[(nc + 1) * 18 + oB] = y3;
                } else if (mt == 1) {
                    int c0 = oA - 16, c1 = oB - 16;
                    kT[nc * 18 + c0] = to_tf32(y0); kT[(nc + 1) * 18 + c0] = to_tf32(y1);
                    kT[nc * 18 + c1] = to_tf32(y2); kT[(nc + 1) * 18 + c1] = to_tf32(y3);
                } else {
                    int dA = oA - 32, dB = oB - 32;
                    if (nc < 196) {
                        vv[dA * 200 + pidx(nc)] = to_tf32(y0);
                        vv[dB * 200 + pidx(nc)] = to_tf32(y2);
                    }
                    if (nc + 1 < 196) {
                        vv[dA * 200 + pidx(nc + 1)] = to_tf32(y1);
                        vv[dB * 200 + pidx(nc + 1)] = to_tf32(y3);
                    }
                }
            }
        }
        __syncthreads();

        // ---------- Phase C ----------
        for (int t = tid; t < KD * NPIX; t += 512) {
            int n = t >> 4, c = t & 15;
            int py = n / RESX, px = n - py * RESX;
            float s = 0.f;
            #pragma unroll
            for (int dy = 0; dy < 5; dy++) {
                int yy = py + dy - 2;
                if (yy < 0 || yy >= RESX) continue;
                #pragma unroll
                for (int dx = 0; dx < 5; dx++) {
                    int xx = px + dx - 2;
                    if (xx < 0 || xx >= RESX) continue;
                    s += dww[c * 25 + dy * 5 + dx] * qT[(yy * RESX + xx) * 18 + c];
                }
            }
            float dq = s * dsc[c] + dbi[c];
            float gl = 0.5f * dq * (1.0f + erff(dq * 0.70710678118654752440f));
            qgT[n * 18 + c] = to_tf32(gl + qT[n * 18 + c]);
        }
        __syncthreads();

        // ---------- Phase D: warp-owned 16-row stripes (warps 0-12);
        //            warps 13-15 prefetch next head's weights ----------
        const float* abm = g_abmat + (size_t)i * (NPIX * NPIX);
        float* gcb = g_cat_t + ((size_t)b * NPIX) * DIM + i * DD;

        if (warp < 13) {
            const int r0 = warp * 16;
            float aq0 = qgT[(r0 + g) * 18 + tig],      aq1 = qgT[(r0 + g + 8) * 18 + tig];
            float aq2 = qgT[(r0 + g) * 18 + tig + 4],  aq3 = qgT[(r0 + g + 8) * 18 + tig + 4];
            float aq4 = qgT[(r0 + g) * 18 + tig + 8],  aq5 = qgT[(r0 + g + 8) * 18 + tig + 8];
            float aq6 = qgT[(r0 + g) * 18 + tig + 12], aq7 = qgT[(r0 + g + 8) * 18 + tig + 12];
            const int ngA = min(r0 + g, 195), ngB = min(r0 + g + 8, 195);
            const float* abrA = abm + (size_t)ngA * NPIX;
            const float* abrB = abm + (size_t)ngB * NPIX;
            const int m0l = 2 * tig;

            // pass 1: row max
            float Mg = -1e30f, Mg8 = -1e30f;
            #pragma unroll 5
            for (int nt = 0; nt < 25; nt++) {
                const int mm0 = nt * 8;
                float b00 = kT[(mm0 + g) * 18 + tig],     b01 = kT[(mm0 + g) * 18 + tig + 4];
                float b10 = kT[(mm0 + g) * 18 + tig + 8], b11 = kT[(mm0 + g) * 18 + tig + 12];
                float dd[4] = {0.f, 0.f, 0.f, 0.f};
                mma8(dd, aq0, aq1, aq2, aq3, b00, b01);
                mma8(dd, aq4, aq5, aq6, aq7, b10, b11);
                const int m0 = mm0 + m0l;
                float2 abA = *(const float2*)&abrA[m0];
                float2 abB = *(const float2*)&abrB[m0];
                float s00 = dd[0] * 0.25f + abA.x;
                float s01 = dd[1] * 0.25f + abA.y;
                float s10 = dd[2] * 0.25f + abB.x;
                float s11 = dd[3] * 0.25f + abB.y;
                if (m0 >= NPIX)     { s00 = -1e30f; s10 = -1e30f; }
                if (m0 + 1 >= NPIX) { s01 = -1e30f; s11 = -1e30f; }
                Mg  = fmaxf(Mg,  fmaxf(s00, s01));
                Mg8 = fmaxf(Mg8, fmaxf(s10, s11));
            }
            Mg  = fmaxf(Mg,  __shfl_xor_sync(0xffffffffu, Mg, 1));
            Mg  = fmaxf(Mg,  __shfl_xor_sync(0xffffffffu, Mg, 2));
            Mg8 = fmaxf(Mg8, __shfl_xor_sync(0xffffffffu, Mg8, 1));
            Mg8 = fmaxf(Mg8, __shfl_xor_sync(0xffffffffu, Mg8, 2));

            // pass 2: exp + AV
            float o[8][4];
            #pragma unroll
            for (int j = 0; j < 8; j++) { o[j][0] = o[j][1] = o[j][2] = o[j][3] = 0.f; }
            float lg = 0.f, lg8 = 0.f;
            const int srcA = (g << 2) | (tig >> 1);
            const int srcB = srcA + 2;
            const bool odd = (tig & 1);

            #pragma unroll 5
            for (int nt = 0; nt < 25; nt++) {
                const int mm0 = nt * 8;
                float b00 = kT[(mm0 + g) * 18 + tig],     b01 = kT[(mm0 + g) * 18 + tig + 4];
                float b10 = kT[(mm0 + g) * 18 + tig + 8], b11 = kT[(mm0 + g) * 18 + tig + 12];
                float dd[4] = {0.f, 0.f, 0.f, 0.f};
                mma8(dd, aq0, aq1, aq2, aq3, b00, b01);
                mma8(dd, aq4, aq5, aq6, aq7, b10, b11);
                const int m0 = mm0 + m0l;
                float2 abA = *(const float2*)&abrA[m0];
                float2 abB = *(const float2*)&abrB[m0];
                float s00 = dd[0] * 0.25f + abA.x;
                float s01 = dd[1] * 0.25f + abA.y;
                float s10 = dd[2] * 0.25f + abB.x;
                float s11 = dd[3] * 0.25f + abB.y;
                if (m0 >= NPIX)     { s00 = -1e30f; s10 = -1e30f; }
                if (m0 + 1 >= NPIX) { s01 = -1e30f; s11 = -1e30f; }
                float p00 = to_tf32(__expf(s00 - Mg));
                float p01 = to_tf32(__expf(s01 - Mg));
                float p10 = to_tf32(__expf(s10 - Mg8));
                float p11 = to_tf32(__expf(s11 - Mg8));
                lg  += p00 + p01;
                lg8 += p10 + p11;
                float t0 = __shfl_sync(0xffffffffu, p00, srcA);
                float t1 = __shfl_sync(0xffffffffu, p01, srcA);
                float a0 = odd ? t1 : t0;
                float u0 = __shfl_sync(0xffffffffu, p10, srcA);
                float u1 = __shfl_sync(0xffffffffu, p11, srcA);
                float a1 = odd ? u1 : u0;
                float t2 = __shfl_sync(0xffffffffu, p00, srcB);
                float t3 = __shfl_sync(0xffffffffu, p01, srcB);
                float a2 = odd ? t3 : t2;
                float u2 = __shfl_sync(0xffffffffu, p10, srcB);
                float u3 = __shfl_sync(0xffffffffu, p11, srcB);
                float a3 = odd ? u3 : u2;
                #pragma unroll
                for (int j = 0; j < 8; j++) {
                    float2 bv = *(const float2*)&vv[(j * 8 + g) * 200 + mm0 + m0l];
                    mma8(o[j], a0, a1, a2, a3, bv.x, bv.y);
                }
            }
            lg  += __shfl_xor_sync(0xffffffffu, lg, 1);
            lg  += __shfl_xor_sync(0xffffffffu, lg, 2);
            lg8 += __shfl_xor_sync(0xffffffffu, lg8, 1);
            lg8 += __shfl_xor_sync(0xffffffffu, lg8, 2);
            float ivg = 1.0f / lg, ivg8 = 1.0f / lg8;

            const int nA = r0 + g, nB = r0 + g + 8;
            #pragma unroll
            for (int j = 0; j < 8; j++) {
                const int dc = j * 8 + 2 * tig;
                if (nA < NPIX) {
                    float v0 = o[j][0] * ivg, v1 = o[j][1] * ivg;
                    *(float2*)&featT[nA * 68 + dc] = make_float2(v0, v1);
                    *(float2*)&gcb[(size_t)nA * DIM + dc] =
                        make_float2(to_tf32(fmaxf(v0, 0.f)), to_tf32(fmaxf(v1, 0.f)));
                }
                if (nB < NPIX) {
                    float v2 = o[j][2] * ivg8, v3 = o[j][3] * ivg8;
                    *(float2*)&featT[nB * 68 + dc] = make_float2(v2, v3);
                    *(float2*)&gcb[(size_t)nB * DIM + dc] =
                        make_float2(to_tf32(fmaxf(v2, 0.f)), to_tf32(fmaxf(v3, 0.f)));
                }
            }
        } else if (i + 1 < NH) {
            // warps 13-15: stage next head's weights (regions unused during Phase D)
            const int t96 = (warp - 13) * 32 + lane;   // 0..95
            const int ih = i + 1;
            for (int idx = t96; idx < QO * 64; idx += 96)
                wq[(idx >> 6) * 68 + (idx & 63)] = to_tf32(qkv_w[ih * QO * 64 + idx]);
            for (int idx = t96; idx < 400; idx += 96)
                dww[idx] = dw_w[ih * 400 + idx];
            if (t96 < 16) {
                dsc[t96] = dw_scale[ih * KD + t96];
                dbi[t96] = dw_bias[ih * KD + t96];
            }
            for (int o = t96; o < QO; o += 96) {
                qsc[o] = qkv_scale[ih * QO + o];
                qbi[o] = qkv_bias[ih * QO + o];
            }
        }
        __syncthreads();
    }
}

// ---------------- prep kernels ----------------
__global__ void wprep_kernel(const float* __restrict__ proj_w) {
    int idx = blockIdx.x * 256 + threadIdx.x;
    g_wt[idx] = to_tf32(proj_w[idx]);
}
__global__ void abprep_kernel(const float* __restrict__ attention_biases,
                              const int* __restrict__ bias_idxs) {
    int idx = blockIdx.x * 256 + threadIdx.x;
    if (idx < NH * NPIX * NPIX) {
        int h = idx / (NPIX * NPIX);
        int nm = idx - h * (NPIX * NPIX);
        g_abmat[idx] = attention_biases[h * NPIX + bias_idxs[nm]];
    }
}

// ---------------- proj kernel: tf32 GEMM, 512 threads, K-chunk=64, double buffer ----------------
#define PJ_NT 128
#define PJ_KC 64
#define PJ_AS 68                          // 64 + 4 pad (same mod-32 bank structure as 36)
#define PJ_A_FLOATS (256 * PJ_AS)         // 17408
#define PJ_B_FLOATS (128 * PJ_AS)         // 8704
#define PJ_BUF_FLOATS (PJ_A_FLOATS + PJ_B_FLOATS)   // 26112
#define PJ_SMEM_BYTES (2 * PJ_BUF_FLOATS * 4)       // 208896

__global__ void __launch_bounds__(512, 1)
proj_mma_kernel(const float* __restrict__ proj_scale,
                const float* __restrict__ proj_bias,
                float* __restrict__ out)
{
    extern __shared__ float smf[];
    const uint32_t smem_base = smem_u32(smf);

    const int tid  = threadIdx.x;
    const int wid  = tid >> 5;        // 0..15
    const int lane = tid & 31;
    const int g    = lane >> 2;
    const int tig  = lane & 3;
    const int n0   = blockIdx.x * PJ_NT;

    const int o0 = (wid & 3) * 64;        // warp M offset
    const int nb = (wid >> 2) * 32;       // warp N offset

    float acc[4][4][4];
    #pragma unroll
    for (int mi = 0; mi < 4; mi++)
        #pragma unroll
        for (int ni = 0; ni < 4; ni++)
            #pragma unroll
            for (int c = 0; c < 4; c++) acc[mi][ni][c] = 0.f;

    auto issue_chunk = [&](int c) {
        const int buf = c & 1;
        const int k0 = c * PJ_KC;
        const uint32_t abase = smem_base + (uint32_t)(buf * PJ_BUF_FLOATS) * 4u;
        const uint32_t bbase = abase + (uint32_t)PJ_A_FLOATS * 4u;
        // A: 256 rows x 16 float4
        #pragma unroll
        for (int it = 0; it < 8; it++) {
            int idx = it * 512 + tid;          // 0..4095
            int row = idx >> 4, k4 = idx & 15;
            CP_ASYNC16(abase + (uint32_t)(row * PJ_AS + k4 * 4) * 4u,
                       g_wt + (size_t)row * 256 + k0 + k4 * 4);
        }
        // B: 128 rows x 16 float4
        #pragma unroll
        for (int it = 0; it < 4; it++) {
            int idx = it * 512 + tid;          // 0..2047
            int row = idx >> 4, k4 = idx & 15;
            CP_ASYNC16(bbase + (uint32_t)(row * PJ_AS + k4 * 4) * 4u,
                       g_cat_t + (size_t)(n0 + row) * 256 + k0 + k4 * 4);
        }
        CP_COMMIT();
    };

    issue_chunk(0);

    for (int c = 0; c < 4; c++) {
        if (c + 1 < 4) issue_chunk(c + 1);
        if (c < 3) CP_WAITG(1);
        else       CP_WAITG(0);
        __syncthreads();

        const int buf = c & 1;
        const uint32_t* Asu = (const uint32_t*)(smf + buf * PJ_BUF_FLOATS);
        const uint32_t* Bsu = Asu + PJ_A_FLOATS;
        const int a_base = (o0 + g) * PJ_AS + tig;
        const int b_base = (nb + g) * PJ_AS + tig;

        #pragma unroll
        for (int k8 = 0; k8 < PJ_KC; k8 += 8) {
            uint32_t a[4][4];
            #pragma unroll
            for (int mi = 0; mi < 4; mi++) {
                int ab = a_base + mi * (16 * PJ_AS) + k8;
                a[mi][0] = Asu[ab];
                a[mi][1] = Asu[ab + 8 * PJ_AS];
                a[mi][2] = Asu[ab + 4];
                a[mi][3] = Asu[ab + 8 * PJ_AS + 4];
            }
            uint32_t bfr[4][2];
            #pragma unroll
            for (int ni = 0; ni < 4; ni++) {
                int bb = b_base + ni * (8 * PJ_AS) + k8;
                bfr[ni][0] = Bsu[bb];
                bfr[ni][1] = Bsu[bb + 4];
            }
            #pragma unroll
            for (int mi = 0; mi < 4; mi++)
                #pragma unroll
                for (int ni = 0; ni < 4; ni++)
                    mma_tf32(acc[mi][ni], a[mi], bfr[ni]);
        }
        __syncthreads();
    }

    // epilogue: two N-halves through smem, coalesced stores
    float* Ssm = smf;
    #pragma unroll
    for (int h = 0; h < 2; h++) {
        __syncthreads();
        if ((wid >> 3) == h) {
            const int nloc = nb - h * 64;   // 0 or 32 within half
            #pragma unroll
            for (int mi = 0; mi < 4; mi++) {
                int orow = o0 + mi * 16 + g;
                #pragma unroll
                for (int ni = 0; ni < 4; ni++) {
                    int nl = nloc + ni * 8 + 2 * tig;
                    *(float2*)&Ssm[orow * 68 + nl] =
                        make_float2(acc[mi][ni][0], acc[mi][ni][1]);
                    *(float2*)&Ssm[(orow + 8) * 68 + nl] =
                        make_float2(acc[mi][ni][2], acc[mi][ni][3]);
                }
            }
        }
        __syncthreads();
        #pragma unroll 4
        for (int it = 0; it < 32; it++) {
            int idx = it * 512 + tid;
            int o = idx >> 6, nn = idx & 63;
            float v = Ssm[o * 68 + nn];
            v = v * proj_scale[o] + proj_bias[o];
            unsigned ng = (unsigned)(n0 + h * 64 + nn);
            unsigned bb = ng / 196u;
            unsigned pp = ng - bb * 196u;
            out[(size_t)bb * (DIM * NPIX) + (size_t)o * NPIX + pp] = v;
        }
    }
}

extern "C" void kernel_launch(void* const* d_in, const int* in_sizes, int n_in,
                              void* d_out, int out_size)
{
    (void)in_sizes; (void)n_in; (void)out_size;
    const float* x          = (const float*)d_in[0];
    const float* qkv_w      = (const float*)d_in[1];
    const float* qkv_scale  = (const float*)d_in[2];
    const float* qkv_bias   = (const float*)d_in[3];
    const float* dw_w       = (const float*)d_in[4];
    const float* dw_scale   = (const float*)d_in[5];
    const float* dw_bias    = (const float*)d_in[6];
    const float* proj_w     = (const float*)d_in[7];
    const float* proj_scale = (const float*)d_in[8];
    const float* proj_bias  = (const float*)d_in[9];
    const float* attn_b     = (const float*)d_in[10];
    const int*   bias_idxs  = (const int*)d_in[11];
    float* out = (float*)d_out;

    cudaFuncSetAttribute(cascade_kernel, cudaFuncAttributeMaxDynamicSharedMemorySize, SMEM1_BYTES);
    cudaFuncSetAttribute(proj_mma_kernel, cudaFuncAttributeMaxDynamicSharedMemorySize, PJ_SMEM_BYTES);

    abprep_kernel<<<(NH * NPIX * NPIX + 255) / 256, 256>>>(attn_b, bias_idxs);
    cascade_kernel<<<BATCH, 512, SMEM1_BYTES>>>(x, qkv_w, qkv_scale, qkv_bias,
                                                dw_w, dw_scale, dw_bias);
    wprep_kernel<<<DIM * DIM / 256, 256>>>(proj_w);
    proj_mma_kernel<<<(BATCH * NPIX) / PJ_NT, 512, PJ_SMEM_BYTES>>>(proj_scale, proj_bias, out);
}